// round 3
// baseline (speedup 1.0000x reference)
#include <cuda_runtime.h>
#include <math.h>
#include <stdint.h>

#define D_MODEL 1024
#define N_HEADS 16
#define D_HEAD  64
#define DECAY   0.99f
#define MAXROWS 4096

// ---------------- scratch (no allocations allowed) ----------------
__device__ float g_Q [MAXROWS * D_MODEL];
__device__ float g_K [MAXROWS * D_MODEL];
__device__ float g_V [MAXROWS * D_MODEL];
__device__ float g_Gp[MAXROWS * D_MODEL];
__device__ float g_R [MAXROWS * D_MODEL];
__device__ float g_NG[MAXROWS * D_MODEL];

// =======================================================================
// TF32 tensor-core GEMM: C = A(MxK) * W(KxN) + bias, K=N=1024.
// 128x128x32 block tile, 8 warps (2x4), warp = 64x32 via m16n8k8.
// Operands staged into fragment-ordered smem (tf32-rounded), double buffered.
// =======================================================================

__device__ __forceinline__ float tf32r(float x) {
    uint32_t u;
    asm("cvt.rna.tf32.f32 %0, %1;" : "=r"(u) : "f"(x));
    return __uint_as_float(u);
}

__device__ __forceinline__ void mma_tf32(float* d, const uint32_t* a, const uint32_t* b) {
    asm volatile(
        "mma.sync.aligned.m16n8k8.row.col.f32.tf32.tf32.f32 "
        "{%0,%1,%2,%3}, {%4,%5,%6,%7}, {%8,%9}, {%0,%1,%2,%3};\n"
        : "+f"(d[0]), "+f"(d[1]), "+f"(d[2]), "+f"(d[3])
        : "r"(a[0]), "r"(a[1]), "r"(a[2]), "r"(a[3]), "r"(b[0]), "r"(b[1]));
}

// A-tile fragment smem: Asf[ksub(4)][mtile(8)][lane(32)][reg(4)]  = 4096 floats
// B-tile fragment smem: Bsf[ksub(4)][ntile(16)][lane(32)][reg(2)] = 4096 floats
#define GEMM_SMEM_FLOATS (4096 + 4096)

__device__ __forceinline__ void ldg_tiles(
    const float* __restrict__ A, const float* __restrict__ W,
    int k0, int row0, int col0, int tid, float4* ra, float4* rb)
{
    #pragma unroll
    for (int it = 0; it < 4; ++it) {
        int f = tid + it * 256;
        int r = f >> 3, c4 = (f & 7) << 2;
        ra[it] = *(const float4*)&A[(size_t)(row0 + r) * 1024 + k0 + c4];
    }
    #pragma unroll
    for (int it = 0; it < 4; ++it) {
        int f = tid + it * 256;
        int kr = f >> 5, c4 = (f & 31) << 2;
        rb[it] = *(const float4*)&W[(size_t)(k0 + kr) * 1024 + col0 + c4];
    }
}

__device__ __forceinline__ void stage_tiles(
    float* __restrict__ As, float* __restrict__ Bs,
    int tid, const float4* ra, const float4* rb)
{
    #pragma unroll
    for (int it = 0; it < 4; ++it) {
        int f = tid + it * 256;
        int r = f >> 3, c4 = (f & 7) << 2;
        int ksub = c4 >> 3;
        int mtile = r >> 4;
        int reg = ((r >> 3) & 1) + (((c4 >> 2) & 1) << 1);
        int lane0 = (r & 7) << 2;
        float* base = &As[(((ksub << 3) + mtile) * 32 + lane0) * 4 + reg];
        base[0]  = tf32r(ra[it].x);
        base[4]  = tf32r(ra[it].y);
        base[8]  = tf32r(ra[it].z);
        base[12] = tf32r(ra[it].w);
    }
    #pragma unroll
    for (int it = 0; it < 4; ++it) {
        int f = tid + it * 256;
        int kr = f >> 5, c4 = (f & 31) << 2;
        int ksub = kr >> 3, kk = kr & 7;
        int reg = kk >> 2;
        int ntile = c4 >> 3, nn = c4 & 7;
        float* base = &Bs[(((ksub << 4) + ntile) * 32 + nn * 4 + (kk & 3)) * 2 + reg];
        base[0]  = tf32r(rb[it].x);
        base[8]  = tf32r(rb[it].y);
        base[16] = tf32r(rb[it].z);
        base[24] = tf32r(rb[it].w);
    }
}

__device__ __forceinline__ void compute_tiles(
    const float* __restrict__ As, const float* __restrict__ Bs,
    float acc[4][4][4], int lane, int warp_m, int warp_n)
{
    #pragma unroll
    for (int ksub = 0; ksub < 4; ++ksub) {
        uint32_t af[4][4], bf[4][2];
        #pragma unroll
        for (int mt = 0; mt < 4; ++mt) {
            float4 v = *(const float4*)&As[(((ksub << 3) + (warp_m << 2) + mt) * 32 + lane) * 4];
            af[mt][0] = __float_as_uint(v.x); af[mt][1] = __float_as_uint(v.y);
            af[mt][2] = __float_as_uint(v.z); af[mt][3] = __float_as_uint(v.w);
        }
        #pragma unroll
        for (int nt = 0; nt < 4; ++nt) {
            float2 v = *(const float2*)&Bs[(((ksub << 4) + (warp_n << 2) + nt) * 32 + lane) * 2];
            bf[nt][0] = __float_as_uint(v.x); bf[nt][1] = __float_as_uint(v.y);
        }
        #pragma unroll
        for (int mt = 0; mt < 4; ++mt)
            #pragma unroll
            for (int nt = 0; nt < 4; ++nt)
                mma_tf32(acc[mt][nt], af[mt], bf[nt]);
    }
}

__device__ __forceinline__ void gemm_tf32_core(
    const float* __restrict__ A, const float* __restrict__ W,
    const float* __restrict__ bias, float* __restrict__ C,
    int row0, int col0)
{
    extern __shared__ float sm[];
    float* Abuf[2] = { sm,        sm + 8192 };
    float* Bbuf[2] = { sm + 4096, sm + 12288 };

    const int tid = threadIdx.x;
    const int lane = tid & 31, wid = tid >> 5;
    const int warp_m = wid >> 2, warp_n = wid & 3;

    float acc[4][4][4] = {};
    float4 ra[4], rb[4];

    ldg_tiles(A, W, 0, row0, col0, tid, ra, rb);
    stage_tiles(Abuf[0], Bbuf[0], tid, ra, rb);
    __syncthreads();

    int cur = 0;
    for (int k0 = 0; k0 < 1024; k0 += 32) {
        const bool has_next = (k0 + 32) < 1024;
        if (has_next) ldg_tiles(A, W, k0 + 32, row0, col0, tid, ra, rb);
        compute_tiles(Abuf[cur], Bbuf[cur], acc, lane, warp_m, warp_n);
        if (has_next) stage_tiles(Abuf[cur ^ 1], Bbuf[cur ^ 1], tid, ra, rb);
        __syncthreads();
        cur ^= 1;
    }

    // epilogue: c0/c1 at (r, c..c+1), c2/c3 at (r+8, c..c+1)
    #pragma unroll
    for (int mt = 0; mt < 4; ++mt) {
        #pragma unroll
        for (int nt = 0; nt < 4; ++nt) {
            int r = row0 + warp_m * 64 + mt * 16 + (lane >> 2);
            int c = col0 + warp_n * 32 + nt * 8 + ((lane & 3) << 1);
            float b0 = bias[c], b1 = bias[c + 1];
            *(float2*)&C[(size_t)r * 1024 + c] =
                make_float2(acc[mt][nt][0] + b0, acc[mt][nt][1] + b1);
            *(float2*)&C[(size_t)(r + 8) * 1024 + c] =
                make_float2(acc[mt][nt][2] + b0, acc[mt][nt][3] + b1);
        }
    }
}

// 4 projections fused: blockIdx.z selects {q,k,v,g}
__global__ __launch_bounds__(256) void proj4_kernel(
    const float* __restrict__ x,
    const float* __restrict__ Wq, const float* __restrict__ bq, float* __restrict__ Qo,
    const float* __restrict__ Wk, const float* __restrict__ bk, float* __restrict__ Ko,
    const float* __restrict__ Wv, const float* __restrict__ bv, float* __restrict__ Vo,
    const float* __restrict__ Wg, const float* __restrict__ bg, float* __restrict__ Go)
{
    const float* W; const float* bias; float* C;
    switch (blockIdx.z) {
        case 0:  W = Wq; bias = bq; C = Qo; break;
        case 1:  W = Wk; bias = bk; C = Ko; break;
        case 2:  W = Wv; bias = bv; C = Vo; break;
        default: W = Wg; bias = bg; C = Go; break;
    }
    gemm_tf32_core(x, W, bias, C, blockIdx.y * 128, blockIdx.x * 128);
}

__global__ __launch_bounds__(256) void sgemm_bias(
    const float* __restrict__ A, const float* __restrict__ W,
    const float* __restrict__ bias, float* __restrict__ C)
{
    gemm_tf32_core(A, W, bias, C, blockIdx.y * 128, blockIdx.x * 128);
}

// =======================================================================
// Retention attention (fp32, unchanged from R2): 128q x 64k tiles.
// =======================================================================
__global__ __launch_bounds__(256, 1) void attn_kernel(
    const float* __restrict__ Q, const float* __restrict__ K,
    const float* __restrict__ V, float* __restrict__ R, int S)
{
    extern __shared__ float sm[];
    float* QsT = sm;                    // [64][132]
    float* KsT = QsT + 64 * 132;        // [64][68]
    float* Vs  = KsT + 64 * 68;         // [64][64]
    float* Ss  = Vs  + 64 * 64;         // [64][132]
    __shared__ float pi[128], pinv[64];

    const int tid = threadIdx.x;
    const int tx = tid & 15;
    const int ty = tid >> 4;
    const int qt = blockIdx.x, h = blockIdx.y, b = blockIdx.z;
    const int i0 = qt * 128;
    const size_t rowbase = (size_t)b * S;
    const int headoff = h * D_HEAD;

    #pragma unroll
    for (int i = 0; i < 8; ++i) {
        int idx = tid + i * 256;
        int q  = idx >> 4;
        int d4 = (idx & 15) * 4;
        float4 v = *(const float4*)&Q[(rowbase + i0 + q) * 1024 + headoff + d4];
        QsT[(d4 + 0) * 132 + q] = v.x; QsT[(d4 + 1) * 132 + q] = v.y;
        QsT[(d4 + 2) * 132 + q] = v.z; QsT[(d4 + 3) * 132 + q] = v.w;
    }
    if (tid < 128)      pi[tid]         = powf(DECAY, (float)tid);
    else if (tid < 192) pinv[tid - 128] = powf(DECAY, -(float)(tid - 128));

    float accO[8][4] = {};
    const int jtmax = 2 * qt + 1;

    for (int jt = 0; jt <= jtmax; ++jt) {
        const int j0 = jt * 64;
        __syncthreads();

        #pragma unroll
        for (int i = 0; i < 4; ++i) {
            int idx = tid + i * 256;
            int k  = idx >> 4;
            int d4 = (idx & 15) * 4;
            size_t g = (rowbase + j0 + k) * 1024 + headoff + d4;
            float4 kv = *(const float4*)&K[g];
            KsT[(d4 + 0) * 68 + k] = kv.x; KsT[(d4 + 1) * 68 + k] = kv.y;
            KsT[(d4 + 2) * 68 + k] = kv.z; KsT[(d4 + 3) * 68 + k] = kv.w;
            *(float4*)&Vs[k * 64 + d4] = *(const float4*)&V[g];
        }
        __syncthreads();

        float accS[8][4] = {};
        #pragma unroll 16
        for (int d = 0; d < 64; ++d) {
            float qv[8], kv[4];
            *(float4*)&qv[0] = *(const float4*)&QsT[d * 132 + ty * 8];
            *(float4*)&qv[4] = *(const float4*)&QsT[d * 132 + ty * 8 + 4];
            *(float4*)&kv[0] = *(const float4*)&KsT[d * 68 + tx * 4];
            #pragma unroll
            for (int m = 0; m < 8; ++m)
                #pragma unroll
                for (int n = 0; n < 4; ++n)
                    accS[m][n] = fmaf(qv[m], kv[n], accS[m][n]);
        }

        const float base = powf(DECAY, (float)(i0 - j0)) * 0.125f;
        const bool maskt = (jt >= 2 * qt);
        const int joff = j0 - i0;
        #pragma unroll
        for (int n = 0; n < 4; ++n) {
            int dj = tx * 4 + n;
            float wj = base * pinv[dj];
            float t[8];
            #pragma unroll
            for (int m = 0; m < 8; ++m) {
                int di = ty * 8 + m;
                float w = wj * pi[di];
                if (maskt && (joff + dj > di)) w = 0.f;
                t[m] = accS[m][n] * w;
            }
            *(float4*)&Ss[dj * 132 + ty * 8]     = make_float4(t[0], t[1], t[2], t[3]);
            *(float4*)&Ss[dj * 132 + ty * 8 + 4] = make_float4(t[4], t[5], t[6], t[7]);
        }
        __syncthreads();

        #pragma unroll 16
        for (int k = 0; k < 64; ++k) {
            float sv[8], vv[4];
            *(float4*)&sv[0] = *(const float4*)&Ss[k * 132 + ty * 8];
            *(float4*)&sv[4] = *(const float4*)&Ss[k * 132 + ty * 8 + 4];
            *(float4*)&vv[0] = *(const float4*)&Vs[k * 64 + tx * 4];
            #pragma unroll
            for (int m = 0; m < 8; ++m)
                #pragma unroll
                for (int n = 0; n < 4; ++n)
                    accO[m][n] = fmaf(sv[m], vv[n], accO[m][n]);
        }
    }

    #pragma unroll
    for (int m = 0; m < 8; ++m) {
        *(float4*)&R[(rowbase + i0 + ty * 8 + m) * 1024 + headoff + tx * 4] =
            make_float4(accO[m][0], accO[m][1], accO[m][2], accO[m][3]);
    }
}

// ---------------- LayerNorm (biased var) + sigmoid gate ----------------
__global__ __launch_bounds__(256) void ln_gate_kernel(
    const float* __restrict__ Rt, const float* __restrict__ Gp,
    const float* __restrict__ gamma, const float* __restrict__ beta,
    float* __restrict__ out)
{
    const int row = blockIdx.x;
    const int tid = threadIdx.x;
    const float* r = Rt + (size_t)row * D_MODEL;

    float s = 0.f, s2 = 0.f;
    #pragma unroll
    for (int c = tid; c < D_MODEL; c += 256) { float v = r[c]; s += v; s2 = fmaf(v, v, s2); }

    __shared__ float red[64];
    #pragma unroll
    for (int off = 16; off; off >>= 1) {
        s  += __shfl_down_sync(0xffffffffu, s,  off);
        s2 += __shfl_down_sync(0xffffffffu, s2, off);
    }
    const int lane = tid & 31, w = tid >> 5;
    if (lane == 0) { red[w] = s; red[32 + w] = s2; }
    __syncthreads();
    if (tid == 0) {
        float S = 0.f, S2 = 0.f;
        #pragma unroll
        for (int i = 0; i < 8; ++i) { S += red[i]; S2 += red[32 + i]; }
        float mu  = S  * (1.f / D_MODEL);
        float var = S2 * (1.f / D_MODEL) - mu * mu;
        red[0] = mu;
        red[1] = rsqrtf(var + 1e-5f);
    }
    __syncthreads();
    const float mu = red[0], inv = red[1];

    const float* gp = Gp + (size_t)row * D_MODEL;
    float* o = out + (size_t)row * D_MODEL;
    #pragma unroll
    for (int c = tid; c < D_MODEL; c += 256) {
        float v = (r[c] - mu) * inv * gamma[c] + beta[c];
        float g = 1.f / (1.f + expf(-gp[c]));
        o[c] = v * g;
    }
}

// ---------------- launch ----------------
extern "C" void kernel_launch(void* const* d_in, const int* in_sizes, int n_in,
                              void* d_out, int out_size)
{
    const float* x     = (const float*)d_in[0];
    const float* Wq    = (const float*)d_in[1];
    const float* bq    = (const float*)d_in[2];
    const float* Wk    = (const float*)d_in[3];
    const float* bk    = (const float*)d_in[4];
    const float* Wv    = (const float*)d_in[5];
    const float* bv    = (const float*)d_in[6];
    const float* Wg    = (const float*)d_in[7];
    const float* bg    = (const float*)d_in[8];
    const float* Wo    = (const float*)d_in[9];
    const float* bo    = (const float*)d_in[10];
    const float* gamma = (const float*)d_in[11];
    const float* beta  = (const float*)d_in[12];
    float* out = (float*)d_out;

    const int M = in_sizes[0] / D_MODEL;   // B*S = 4096
    const int B = 2;
    const int S = M / B;                   // 2048

    float *Qd, *Kd, *Vd, *Gpd, *Rd, *NGd;
    cudaGetSymbolAddress((void**)&Qd,  g_Q);
    cudaGetSymbolAddress((void**)&Kd,  g_K);
    cudaGetSymbolAddress((void**)&Vd,  g_V);
    cudaGetSymbolAddress((void**)&Gpd, g_Gp);
    cudaGetSymbolAddress((void**)&Rd,  g_R);
    cudaGetSymbolAddress((void**)&NGd, g_NG);

    const int GEMM_SMEM = 2 * GEMM_SMEM_FLOATS * (int)sizeof(float);  // 65536
    cudaFuncSetAttribute(proj4_kernel, cudaFuncAttributeMaxDynamicSharedMemorySize, GEMM_SMEM);
    cudaFuncSetAttribute(sgemm_bias,   cudaFuncAttributeMaxDynamicSharedMemorySize, GEMM_SMEM);

    dim3 pg(D_MODEL / 128, M / 128, 4);
    proj4_kernel<<<pg, 256, GEMM_SMEM>>>(x, Wq, bq, Qd, Wk, bk, Kd, Wv, bv, Vd, Wg, bg, Gpd);

    const int ATT_SMEM = (64 * 132 + 64 * 68 + 64 * 64 + 64 * 132) * (int)sizeof(float);
    cudaFuncSetAttribute(attn_kernel, cudaFuncAttributeMaxDynamicSharedMemorySize, ATT_SMEM);
    attn_kernel<<<dim3(S / 128, N_HEADS, B), 256, ATT_SMEM>>>(Qd, Kd, Vd, Rd, S);

    ln_gate_kernel<<<M, 256>>>(Rd, Gpd, gamma, beta, NGd);

    sgemm_bias<<<dim3(D_MODEL / 128, M / 128), 256, GEMM_SMEM>>>(NGd, Wo, bo, out);
}

// round 7
// speedup vs baseline: 1.5762x; 1.5762x over previous
#include <cuda_runtime.h>
#include <math.h>
#include <stdint.h>

#define D_MODEL 1024
#define N_HEADS 16
#define D_HEAD  64
#define DECAY   0.99f
#define MAXROWS 4096
#define NCHUNK  16          // S/128
#define CHUNK   128

// ---------------- scratch (no allocations allowed) ----------------
__device__ float g_Q [MAXROWS * D_MODEL];
__device__ float g_K [MAXROWS * D_MODEL];
__device__ float g_V [MAXROWS * D_MODEL];
__device__ float g_Gp[MAXROWS * D_MODEL];
__device__ float g_R [MAXROWS * D_MODEL];
__device__ float g_NG[MAXROWS * D_MODEL];
__device__ float g_KV[2 * N_HEADS * NCHUNK * 64 * 64];   // per (b,h,c) 64x64
__device__ float g_St[2 * N_HEADS * NCHUNK * 64 * 64];

// =======================================================================
// 128x128x16 SGEMM, 8x8 microtile, double-buffered smem (R2 math, 1 sync/iter)
// =======================================================================
__device__ __forceinline__ void gemm128_db(
    const float* __restrict__ A, const float* __restrict__ W,
    const float* __restrict__ bias, float* __restrict__ C,
    int row0, int col0)
{
    __shared__ float As[2][16][132];
    __shared__ float Bs[2][16][128];

    const int tid = threadIdx.x;
    const int tx = tid & 15, ty = tid >> 4;

    float acc[8][8] = {};
    float4 ra[2], rb[2];

    // ldg k0=0
    #pragma unroll
    for (int i = 0; i < 2; ++i) {
        int idx = tid + i * 256;
        int r = idx >> 2, c4 = (idx & 3) * 4;
        ra[i] = *(const float4*)&A[(size_t)(row0 + r) * 1024 + c4];
    }
    #pragma unroll
    for (int i = 0; i < 2; ++i) {
        int idx = tid + i * 256;
        int r = idx >> 5, c4 = (idx & 31) * 4;
        rb[i] = *(const float4*)&W[(size_t)r * 1024 + col0 + c4];
    }
    // sts -> buf0
    #pragma unroll
    for (int i = 0; i < 2; ++i) {
        int idx = tid + i * 256;
        int r = idx >> 2, c4 = (idx & 3) * 4;
        As[0][c4 + 0][r] = ra[i].x; As[0][c4 + 1][r] = ra[i].y;
        As[0][c4 + 2][r] = ra[i].z; As[0][c4 + 3][r] = ra[i].w;
    }
    #pragma unroll
    for (int i = 0; i < 2; ++i) {
        int idx = tid + i * 256;
        int r = idx >> 5, c4 = (idx & 31) * 4;
        *(float4*)&Bs[0][r][c4] = rb[i];
    }
    __syncthreads();

    #pragma unroll 1
    for (int it = 0; it < 64; ++it) {
        const int buf = it & 1;
        if (it < 63) {
            const int k0 = (it + 1) * 16;
            #pragma unroll
            for (int i = 0; i < 2; ++i) {
                int idx = tid + i * 256;
                int r = idx >> 2, c4 = (idx & 3) * 4;
                ra[i] = *(const float4*)&A[(size_t)(row0 + r) * 1024 + k0 + c4];
            }
            #pragma unroll
            for (int i = 0; i < 2; ++i) {
                int idx = tid + i * 256;
                int r = idx >> 5, c4 = (idx & 31) * 4;
                rb[i] = *(const float4*)&W[(size_t)(k0 + r) * 1024 + col0 + c4];
            }
        }
        #pragma unroll
        for (int kk = 0; kk < 16; ++kk) {
            float a[8], b[8];
            *(float4*)&a[0] = *(const float4*)&As[buf][kk][ty * 8];
            *(float4*)&a[4] = *(const float4*)&As[buf][kk][ty * 8 + 4];
            *(float4*)&b[0] = *(const float4*)&Bs[buf][kk][tx * 8];
            *(float4*)&b[4] = *(const float4*)&Bs[buf][kk][tx * 8 + 4];
            #pragma unroll
            for (int m = 0; m < 8; ++m)
                #pragma unroll
                for (int n = 0; n < 8; ++n)
                    acc[m][n] = fmaf(a[m], b[n], acc[m][n]);
        }
        if (it < 63) {
            const int nb = buf ^ 1;
            #pragma unroll
            for (int i = 0; i < 2; ++i) {
                int idx = tid + i * 256;
                int r = idx >> 2, c4 = (idx & 3) * 4;
                As[nb][c4 + 0][r] = ra[i].x; As[nb][c4 + 1][r] = ra[i].y;
                As[nb][c4 + 2][r] = ra[i].z; As[nb][c4 + 3][r] = ra[i].w;
            }
            #pragma unroll
            for (int i = 0; i < 2; ++i) {
                int idx = tid + i * 256;
                int r = idx >> 5, c4 = (idx & 31) * 4;
                *(float4*)&Bs[nb][r][c4] = rb[i];
            }
        }
        __syncthreads();
    }

    float bv[8];
    *(float4*)&bv[0] = *(const float4*)&bias[col0 + tx * 8];
    *(float4*)&bv[4] = *(const float4*)&bias[col0 + tx * 8 + 4];
    #pragma unroll
    for (int m = 0; m < 8; ++m) {
        size_t rbase = (size_t)(row0 + ty * 8 + m) * 1024 + col0 + tx * 8;
        *(float4*)&C[rbase]     = make_float4(acc[m][0] + bv[0], acc[m][1] + bv[1],
                                              acc[m][2] + bv[2], acc[m][3] + bv[3]);
        *(float4*)&C[rbase + 4] = make_float4(acc[m][4] + bv[4], acc[m][5] + bv[5],
                                              acc[m][6] + bv[6], acc[m][7] + bv[7]);
    }
}

__global__ __launch_bounds__(256, 2) void proj4_kernel(
    const float* __restrict__ x,
    const float* __restrict__ Wq, const float* __restrict__ bq, float* __restrict__ Qo,
    const float* __restrict__ Wk, const float* __restrict__ bk, float* __restrict__ Ko,
    const float* __restrict__ Wv, const float* __restrict__ bv, float* __restrict__ Vo,
    const float* __restrict__ Wg, const float* __restrict__ bg, float* __restrict__ Go)
{
    const float* W; const float* bias; float* C;
    switch (blockIdx.z) {
        case 0:  W = Wq; bias = bq; C = Qo; break;
        case 1:  W = Wk; bias = bk; C = Ko; break;
        case 2:  W = Wv; bias = bv; C = Vo; break;
        default: W = Wg; bias = bg; C = Go; break;
    }
    gemm128_db(x, W, bias, C, blockIdx.y * 128, blockIdx.x * 128);
}

__global__ __launch_bounds__(256, 2) void sgemm_bias(
    const float* __restrict__ A, const float* __restrict__ W,
    const float* __restrict__ bias, float* __restrict__ C)
{
    gemm128_db(A, W, bias, C, blockIdx.y * 128, blockIdx.x * 128);
}

// =======================================================================
// Chunkwise retention, stage A: KV_c[d][e] = sum_lj decay^(-lj) k[lj][d] v[lj][e]
// grid (c=16, h=16, b=2), 256 threads
// =======================================================================
__global__ __launch_bounds__(256) void kv_kernel(
    const float* __restrict__ K, const float* __restrict__ V,
    float* __restrict__ KV, int S)
{
    __shared__ float Ks[64][68];
    __shared__ float Vs[64][68];
    __shared__ float pw[128];

    const int tid = threadIdx.x;
    const int tx = tid & 15, ty = tid >> 4;
    const int c = blockIdx.x, h = blockIdx.y, b = blockIdx.z;
    const int headoff = h * D_HEAD;

    if (tid < 128) pw[tid] = powf(DECAY, -(float)tid);

    float acc[4][4] = {};

    #pragma unroll
    for (int half = 0; half < 2; ++half) {
        __syncthreads();
        #pragma unroll
        for (int i = 0; i < 4; ++i) {
            int idx = tid + i * 256;
            int r = idx >> 4, c4 = (idx & 15) * 4;
            size_t row = (size_t)b * S + c * CHUNK + half * 64 + r;
            float4 kv = *(const float4*)&K[row * 1024 + headoff + c4];
            float w = pw[half * 64 + r];
            Ks[r][c4 + 0] = kv.x * w; Ks[r][c4 + 1] = kv.y * w;
            Ks[r][c4 + 2] = kv.z * w; Ks[r][c4 + 3] = kv.w * w;
            *(float4*)&Vs[r][c4] = *(const float4*)&V[row * 1024 + headoff + c4];
        }
        __syncthreads();
        #pragma unroll 8
        for (int lj = 0; lj < 64; ++lj) {
            float a[4], bb[4];
            *(float4*)&a[0]  = *(const float4*)&Ks[lj][ty * 4];
            *(float4*)&bb[0] = *(const float4*)&Vs[lj][tx * 4];
            #pragma unroll
            for (int m = 0; m < 4; ++m)
                #pragma unroll
                for (int n = 0; n < 4; ++n)
                    acc[m][n] = fmaf(a[m], bb[n], acc[m][n]);
        }
    }

    float* out = KV + (((size_t)(b * N_HEADS + h) * NCHUNK + c) << 12);
    #pragma unroll
    for (int m = 0; m < 4; ++m)
        *(float4*)&out[(ty * 4 + m) * 64 + tx * 4] =
            make_float4(acc[m][0], acc[m][1], acc[m][2], acc[m][3]);
}

// stage B: State_c = decay^128 * (State_{c-1} + KV_{c-1}), State_0 = 0
// grid 32 = (b*h), 256 threads, 16 entries each
__global__ __launch_bounds__(256) void scan_kernel(
    const float* __restrict__ KV, float* __restrict__ St)
{
    const int tid = threadIdx.x;
    const size_t base = (size_t)blockIdx.x * NCHUNK * 4096;
    const float dC = powf(DECAY, (float)CHUNK);

    float state[16];
    #pragma unroll
    for (int r = 0; r < 16; ++r) state[r] = 0.f;

    for (int c = 0; c < NCHUNK; ++c) {
        const size_t o = base + (size_t)c * 4096 + tid;
        #pragma unroll
        for (int r = 0; r < 16; ++r) St[o + r * 256] = state[r];
        #pragma unroll
        for (int r = 0; r < 16; ++r) state[r] = dC * (state[r] + KV[o + r * 256]);
    }
}

// =======================================================================
// stage C: per (qchunk, h, b): intra-chunk (2 masked 64-key tiles) + state term
// retained = intra + 0.125 * decay^li * (q . State_c)
// =======================================================================
__global__ __launch_bounds__(256, 1) void attn_chunk_kernel(
    const float* __restrict__ Q, const float* __restrict__ K,
    const float* __restrict__ V, const float* __restrict__ St,
    float* __restrict__ R, int S)
{
    extern __shared__ float sm[];
    float* QsT = sm;                    // [64][132]  (d, q)
    float* KsT = QsT + 64 * 132;        // [64][68]   (d, k) ; first used as State[d][e]
    float* Vs  = KsT + 64 * 68;         // [64][64]
    float* Ss  = Vs  + 64 * 64;         // [64][132]
    __shared__ float pi[128], pinv[64];

    const int tid = threadIdx.x;
    const int tx = tid & 15;
    const int ty = tid >> 4;
    const int qt = blockIdx.x, h = blockIdx.y, b = blockIdx.z;
    const int i0 = qt * CHUNK;
    const size_t rowbase = (size_t)b * S;
    const int headoff = h * D_HEAD;

    // load Q tile (128 x 64) transposed
    #pragma unroll
    for (int i = 0; i < 8; ++i) {
        int idx = tid + i * 256;
        int q  = idx >> 4;
        int d4 = (idx & 15) * 4;
        float4 v = *(const float4*)&Q[(rowbase + i0 + q) * 1024 + headoff + d4];
        QsT[(d4 + 0) * 132 + q] = v.x; QsT[(d4 + 1) * 132 + q] = v.y;
        QsT[(d4 + 2) * 132 + q] = v.z; QsT[(d4 + 3) * 132 + q] = v.w;
    }
    // load State_c[d][e] into KsT area ([d*68 + e]); 64 rows x 16 float4/row
    {
        const float* Sp = St + (((size_t)(b * N_HEADS + h) * NCHUNK + qt) << 12);
        #pragma unroll
        for (int i = 0; i < 4; ++i) {
            int idx = tid + i * 256;
            int d = idx >> 4, e4 = (idx & 15) * 4;
            *(float4*)&KsT[d * 68 + e4] = *(const float4*)&Sp[d * 64 + e4];
        }
    }
    if (tid < 128)      pi[tid]         = powf(DECAY, (float)tid);
    else if (tid < 192) pinv[tid - 128] = powf(DECAY, -(float)(tid - 128));
    __syncthreads();

    // state GEMM: accSt[q][e] = sum_d Q[q][d] * State[d][e]
    float accO[8][4];
    {
        float accSt[8][4] = {};
        #pragma unroll 16
        for (int d = 0; d < 64; ++d) {
            float qv[8], sv[4];
            *(float4*)&qv[0] = *(const float4*)&QsT[d * 132 + ty * 8];
            *(float4*)&qv[4] = *(const float4*)&QsT[d * 132 + ty * 8 + 4];
            *(float4*)&sv[0] = *(const float4*)&KsT[d * 68 + tx * 4];
            #pragma unroll
            for (int m = 0; m < 8; ++m)
                #pragma unroll
                for (int n = 0; n < 4; ++n)
                    accSt[m][n] = fmaf(qv[m], sv[n], accSt[m][n]);
        }
        #pragma unroll
        for (int m = 0; m < 8; ++m) {
            float w = 0.125f * pi[ty * 8 + m];
            #pragma unroll
            for (int n = 0; n < 4; ++n) accO[m][n] = w * accSt[m][n];
        }
    }

    // intra-chunk: two 64-key tiles, both causally masked
    #pragma unroll 1
    for (int jt2 = 0; jt2 < 2; ++jt2) {
        const int j0 = i0 + jt2 * 64;
        __syncthreads();   // state GEMM / prev iter done with KsT, Vs, Ss

        #pragma unroll
        for (int i = 0; i < 4; ++i) {
            int idx = tid + i * 256;
            int k  = idx >> 4;
            int d4 = (idx & 15) * 4;
            size_t g = (rowbase + j0 + k) * 1024 + headoff + d4;
            float4 kv = *(const float4*)&K[g];
            KsT[(d4 + 0) * 68 + k] = kv.x; KsT[(d4 + 1) * 68 + k] = kv.y;
            KsT[(d4 + 2) * 68 + k] = kv.z; KsT[(d4 + 3) * 68 + k] = kv.w;
            *(float4*)&Vs[k * 64 + d4] = *(const float4*)&V[g];
        }
        __syncthreads();

        float accS[8][4] = {};
        #pragma unroll 16
        for (int d = 0; d < 64; ++d) {
            float qv[8], kv[4];
            *(float4*)&qv[0] = *(const float4*)&QsT[d * 132 + ty * 8];
            *(float4*)&qv[4] = *(const float4*)&QsT[d * 132 + ty * 8 + 4];
            *(float4*)&kv[0] = *(const float4*)&KsT[d * 68 + tx * 4];
            #pragma unroll
            for (int m = 0; m < 8; ++m)
                #pragma unroll
                for (int n = 0; n < 4; ++n)
                    accS[m][n] = fmaf(qv[m], kv[n], accS[m][n]);
        }

        const float base = powf(DECAY, (float)(i0 - j0)) * 0.125f;
        const int joff = j0 - i0;
        #pragma unroll
        for (int n = 0; n < 4; ++n) {
            int dj = tx * 4 + n;
            float wj = base * pinv[dj];
            float t[8];
            #pragma unroll
            for (int m = 0; m < 8; ++m) {
                int di = ty * 8 + m;
                float w = wj * pi[di];
                if (joff + dj > di) w = 0.f;
                t[m] = accS[m][n] * w;
            }
            *(float4*)&Ss[dj * 132 + ty * 8]     = make_float4(t[0], t[1], t[2], t[3]);
            *(float4*)&Ss[dj * 132 + ty * 8 + 4] = make_float4(t[4], t[5], t[6], t[7]);
        }
        __syncthreads();

        #pragma unroll 16
        for (int k = 0; k < 64; ++k) {
            float sv[8], vv[4];
            *(float4*)&sv[0] = *(const float4*)&Ss[k * 132 + ty * 8];
            *(float4*)&sv[4] = *(const float4*)&Ss[k * 132 + ty * 8 + 4];
            *(float4*)&vv[0] = *(const float4*)&Vs[k * 64 + tx * 4];
            #pragma unroll
            for (int m = 0; m < 8; ++m)
                #pragma unroll
                for (int n = 0; n < 4; ++n)
                    accO[m][n] = fmaf(sv[m], vv[n], accO[m][n]);
        }
    }

    #pragma unroll
    for (int m = 0; m < 8; ++m) {
        *(float4*)&R[(rowbase + i0 + ty * 8 + m) * 1024 + headoff + tx * 4] =
            make_float4(accO[m][0], accO[m][1], accO[m][2], accO[m][3]);
    }
}

// ---------------- LayerNorm (biased var) + sigmoid gate ----------------
__global__ __launch_bounds__(256) void ln_gate_kernel(
    const float* __restrict__ Rt, const float* __restrict__ Gp,
    const float* __restrict__ gamma, const float* __restrict__ beta,
    float* __restrict__ out)
{
    const int row = blockIdx.x;
    const int tid = threadIdx.x;
    const float* r = Rt + (size_t)row * D_MODEL;

    float s = 0.f, s2 = 0.f;
    #pragma unroll
    for (int c = tid; c < D_MODEL; c += 256) { float v = r[c]; s += v; s2 = fmaf(v, v, s2); }

    __shared__ float red[64];
    #pragma unroll
    for (int off = 16; off; off >>= 1) {
        s  += __shfl_down_sync(0xffffffffu, s,  off);
        s2 += __shfl_down_sync(0xffffffffu, s2, off);
    }
    const int lane = tid & 31, w = tid >> 5;
    if (lane == 0) { red[w] = s; red[32 + w] = s2; }
    __syncthreads();
    if (tid == 0) {
        float S = 0.f, S2 = 0.f;
        #pragma unroll
        for (int i = 0; i < 8; ++i) { S += red[i]; S2 += red[32 + i]; }
        float mu  = S  * (1.f / D_MODEL);
        float var = S2 * (1.f / D_MODEL) - mu * mu;
        red[0] = mu;
        red[1] = rsqrtf(var + 1e-5f);
    }
    __syncthreads();
    const float mu = red[0], inv = red[1];

    const float* gp = Gp + (size_t)row * D_MODEL;
    float* o = out + (size_t)row * D_MODEL;
    #pragma unroll
    for (int c = tid; c < D_MODEL; c += 256) {
        float v = (r[c] - mu) * inv * gamma[c] + beta[c];
        float g = 1.f / (1.f + expf(-gp[c]));
        o[c] = v * g;
    }
}

// ---------------- launch ----------------
extern "C" void kernel_launch(void* const* d_in, const int* in_sizes, int n_in,
                              void* d_out, int out_size)
{
    const float* x     = (const float*)d_in[0];
    const float* Wq    = (const float*)d_in[1];
    const float* bq    = (const float*)d_in[2];
    const float* Wk    = (const float*)d_in[3];
    const float* bk    = (const float*)d_in[4];
    const float* Wv    = (const float*)d_in[5];
    const float* bv    = (const float*)d_in[6];
    const float* Wg    = (const float*)d_in[7];
    const float* bg    = (const float*)d_in[8];
    const float* Wo    = (const float*)d_in[9];
    const float* bo    = (const float*)d_in[10];
    const float* gamma = (const float*)d_in[11];
    const float* beta  = (const float*)d_in[12];
    float* out = (float*)d_out;

    const int M = in_sizes[0] / D_MODEL;   // B*S = 4096
    const int B = 2;
    const int S = M / B;                   // 2048

    float *Qd, *Kd, *Vd, *Gpd, *Rd, *NGd, *KVd, *Std;
    cudaGetSymbolAddress((void**)&Qd,  g_Q);
    cudaGetSymbolAddress((void**)&Kd,  g_K);
    cudaGetSymbolAddress((void**)&Vd,  g_V);
    cudaGetSymbolAddress((void**)&Gpd, g_Gp);
    cudaGetSymbolAddress((void**)&Rd,  g_R);
    cudaGetSymbolAddress((void**)&NGd, g_NG);
    cudaGetSymbolAddress((void**)&KVd, g_KV);
    cudaGetSymbolAddress((void**)&Std, g_St);

    // 1) fused 4-way projection
    dim3 pg(D_MODEL / 128, M / 128, 4);
    proj4_kernel<<<pg, 256>>>(x, Wq, bq, Qd, Wk, bk, Kd, Wv, bv, Vd, Wg, bg, Gpd);

    // 2) chunkwise retention: KV build -> scan -> per-chunk attention
    kv_kernel<<<dim3(NCHUNK, N_HEADS, B), 256>>>(Kd, Vd, KVd, S);
    scan_kernel<<<B * N_HEADS, 256>>>(KVd, Std);

    const int ATT_SMEM = (64 * 132 + 64 * 68 + 64 * 64 + 64 * 132) * (int)sizeof(float);
    cudaFuncSetAttribute(attn_chunk_kernel, cudaFuncAttributeMaxDynamicSharedMemorySize, ATT_SMEM);
    attn_chunk_kernel<<<dim3(S / CHUNK, N_HEADS, B), 256, ATT_SMEM>>>(Qd, Kd, Vd, Std, Rd, S);

    // 3) LN + gate
    ln_gate_kernel<<<M, 256>>>(Rd, Gpd, gamma, beta, NGd);

    // 4) output projection
    sgemm_bias<<<dim3(D_MODEL / 128, M / 128), 256>>>(NGd, Wo, bo, out);
}

// round 8
// speedup vs baseline: 3.2637x; 2.0706x over previous
#include <cuda_runtime.h>
#include <math.h>
#include <stdint.h>

#define D_MODEL 1024
#define N_HEADS 16
#define D_HEAD  64
#define DECAY   0.99f
#define MAXROWS 4096
#define NCHUNK  16
#define CHUNK   128

// ---------------- scratch ----------------
__device__ float g_Q [MAXROWS * D_MODEL];
__device__ float g_K [MAXROWS * D_MODEL];
__device__ float g_V [MAXROWS * D_MODEL];
__device__ float g_Gp[MAXROWS * D_MODEL];
__device__ float g_R [MAXROWS * D_MODEL];
__device__ float g_NG[MAXROWS * D_MODEL];
__device__ float g_KV[2 * N_HEADS * NCHUNK * 64 * 64];
__device__ float g_St[2 * N_HEADS * NCHUNK * 64 * 64];
__device__ float g_Xc[MAXROWS * D_MODEL];          // tf32-rounded activations
__device__ float g_Wt[5 * D_MODEL * D_MODEL];      // tf32-rounded transposed weights

__device__ __forceinline__ float tf32r(float x) {
    uint32_t u;
    asm("cvt.rna.tf32.f32 %0, %1;" : "=r"(u) : "f"(x));
    return __uint_as_float(u);
}
__device__ __forceinline__ void mma_tf32(float* d, const uint32_t* a, const uint32_t* b) {
    asm volatile(
        "mma.sync.aligned.m16n8k8.row.col.f32.tf32.tf32.f32 "
        "{%0,%1,%2,%3}, {%4,%5,%6,%7}, {%8,%9}, {%0,%1,%2,%3};\n"
        : "+f"(d[0]), "+f"(d[1]), "+f"(d[2]), "+f"(d[3])
        : "r"(a[0]), "r"(a[1]), "r"(a[2]), "r"(a[3]), "r"(b[0]), "r"(b[1]));
}

// ---------------- pre-conversion ----------------
__global__ __launch_bounds__(256) void cvt_tf32_vec(
    const float* __restrict__ in, float* __restrict__ out)
{
    int i = blockIdx.x * 256 + threadIdx.x;
    float4 v = ((const float4*)in)[i];
    v.x = tf32r(v.x); v.y = tf32r(v.y); v.z = tf32r(v.z); v.w = tf32r(v.w);
    ((float4*)out)[i] = v;
}

// Wt[z][n][k] = tf32(W_z[k][n])
__global__ __launch_bounds__(256) void wtrans5_kernel(
    const float* __restrict__ W0, const float* __restrict__ W1,
    const float* __restrict__ W2, const float* __restrict__ W3,
    const float* __restrict__ W4, float* __restrict__ Wt)
{
    __shared__ float t[32][33];
    const float* W;
    switch (blockIdx.z) {
        case 0: W = W0; break; case 1: W = W1; break;
        case 2: W = W2; break; case 3: W = W3; break;
        default: W = W4; break;
    }
    float* out = Wt + (size_t)blockIdx.z * D_MODEL * D_MODEL;
    const int bx = blockIdx.x * 32, by = blockIdx.y * 32;
    const int tx = threadIdx.x & 31, ty = threadIdx.x >> 5;

    #pragma unroll
    for (int i = 0; i < 4; ++i)
        t[ty * 4 + i][tx] = W[(size_t)(by + ty * 4 + i) * 1024 + bx + tx];
    __syncthreads();
    #pragma unroll
    for (int i = 0; i < 4; ++i)
        out[(size_t)(bx + ty * 4 + i) * 1024 + by + tx] = tf32r(t[tx][ty * 4 + i]);
}

// =======================================================================
// TF32 mma.sync GEMM v3: C = A*W + bias.  A tf32 [m][k]; Wt tf32 [n][k].
// 128x128 tile, BK=16, register-staged LDG->STS double buffer (R7 pattern),
// padded [row][20] smem -> conflict-free LDS fragment loads.
// 8 warps (2x4), warp tile 64x32 via m16n8k8.
// =======================================================================
#define ASTR 20
#define TILEF (128 * ASTR)

__device__ __forceinline__ void gemm_tf32_v3(
    const float* __restrict__ A, const float* __restrict__ Wt,
    const float* __restrict__ bias, float* __restrict__ C,
    int row0, int col0)
{
    __shared__ float As[2][TILEF];
    __shared__ float Bs[2][TILEF];

    const int tid = threadIdx.x;
    const int lane = tid & 31, wid = tid >> 5;
    const int wm = wid >> 2, wn = wid & 3;
    const int lr = lane >> 2, lk = lane & 3;
    const int sr = tid >> 2, sc4 = (tid & 3) << 2;   // staging: row 0..63(+64), col 0..12

    float acc[4][4][4] = {};
    float4 ra[2], rb[2];

    // prologue: LDG k0=0, STS buf0
    #pragma unroll
    for (int i = 0; i < 2; ++i) {
        ra[i] = *(const float4*)&A [(size_t)(row0 + sr + i * 64) * 1024 + sc4];
        rb[i] = *(const float4*)&Wt[(size_t)(col0 + sr + i * 64) * 1024 + sc4];
    }
    #pragma unroll
    for (int i = 0; i < 2; ++i) {
        *(float4*)&As[0][(sr + i * 64) * ASTR + sc4] = ra[i];
        *(float4*)&Bs[0][(sr + i * 64) * ASTR + sc4] = rb[i];
    }
    __syncthreads();

    #pragma unroll 1
    for (int it = 0; it < 64; ++it) {
        const int buf = it & 1;
        if (it < 63) {
            const int k0 = (it + 1) * 16;
            #pragma unroll
            for (int i = 0; i < 2; ++i) {
                ra[i] = *(const float4*)&A [(size_t)(row0 + sr + i * 64) * 1024 + k0 + sc4];
                rb[i] = *(const float4*)&Wt[(size_t)(col0 + sr + i * 64) * 1024 + k0 + sc4];
            }
        }
        const float* Ab = As[buf];
        const float* Bb = Bs[buf];
        #pragma unroll
        for (int ks = 0; ks < 2; ++ks) {
            const int kb = ks * 8 + lk;
            uint32_t af[4][4], bf[4][2];
            #pragma unroll
            for (int mt = 0; mt < 4; ++mt) {
                const float* ap = Ab + (wm * 64 + mt * 16 + lr) * ASTR + kb;
                af[mt][0] = __float_as_uint(ap[0]);
                af[mt][1] = __float_as_uint(ap[8 * ASTR]);
                af[mt][2] = __float_as_uint(ap[4]);
                af[mt][3] = __float_as_uint(ap[8 * ASTR + 4]);
            }
            #pragma unroll
            for (int nt = 0; nt < 4; ++nt) {
                const float* bp = Bb + (wn * 32 + nt * 8 + lr) * ASTR + kb;
                bf[nt][0] = __float_as_uint(bp[0]);
                bf[nt][1] = __float_as_uint(bp[4]);
            }
            #pragma unroll
            for (int mt = 0; mt < 4; ++mt)
                #pragma unroll
                for (int nt = 0; nt < 4; ++nt)
                    mma_tf32(acc[mt][nt], af[mt], bf[nt]);
        }
        if (it < 63) {
            const int nb = buf ^ 1;
            #pragma unroll
            for (int i = 0; i < 2; ++i) {
                *(float4*)&As[nb][(sr + i * 64) * ASTR + sc4] = ra[i];
                *(float4*)&Bs[nb][(sr + i * 64) * ASTR + sc4] = rb[i];
            }
        }
        __syncthreads();
    }

    // epilogue (R3-proven mapping)
    #pragma unroll
    for (int mt = 0; mt < 4; ++mt) {
        #pragma unroll
        for (int nt = 0; nt < 4; ++nt) {
            int r = row0 + wm * 64 + mt * 16 + lr;
            int c = col0 + wn * 32 + nt * 8 + lk * 2;
            float b0 = bias[c], b1 = bias[c + 1];
            *(float2*)&C[(size_t)r * 1024 + c] =
                make_float2(acc[mt][nt][0] + b0, acc[mt][nt][1] + b1);
            *(float2*)&C[(size_t)(r + 8) * 1024 + c] =
                make_float2(acc[mt][nt][2] + b0, acc[mt][nt][3] + b1);
        }
    }
}

__global__ __launch_bounds__(256, 2) void proj4_kernel(
    const float* __restrict__ xc, const float* __restrict__ Wt,
    const float* __restrict__ bq, const float* __restrict__ bk,
    const float* __restrict__ bv, const float* __restrict__ bg,
    float* __restrict__ Qo, float* __restrict__ Ko,
    float* __restrict__ Vo, float* __restrict__ Go)
{
    const float* bias; float* C;
    switch (blockIdx.z) {
        case 0:  bias = bq; C = Qo; break;
        case 1:  bias = bk; C = Ko; break;
        case 2:  bias = bv; C = Vo; break;
        default: bias = bg; C = Go; break;
    }
    gemm_tf32_v3(xc, Wt + (size_t)blockIdx.z * D_MODEL * D_MODEL, bias, C,
                 blockIdx.y * 128, blockIdx.x * 128);
}

__global__ __launch_bounds__(256, 2) void sgemm_out(
    const float* __restrict__ A, const float* __restrict__ Wt,
    const float* __restrict__ bias, float* __restrict__ C)
{
    gemm_tf32_v3(A, Wt, bias, C, blockIdx.y * 128, blockIdx.x * 128);
}

// =======================================================================
// Chunkwise retention (proven R7): KV build -> scan -> per-chunk attention
// =======================================================================
__global__ __launch_bounds__(256) void kv_kernel(
    const float* __restrict__ K, const float* __restrict__ V,
    float* __restrict__ KV, int S)
{
    __shared__ float Ks[64][68];
    __shared__ float Vs[64][68];
    __shared__ float pw[128];

    const int tid = threadIdx.x;
    const int tx = tid & 15, ty = tid >> 4;
    const int c = blockIdx.x, h = blockIdx.y, b = blockIdx.z;
    const int headoff = h * D_HEAD;

    if (tid < 128) pw[tid] = powf(DECAY, -(float)tid);

    float acc[4][4] = {};

    #pragma unroll
    for (int half = 0; half < 2; ++half) {
        __syncthreads();
        #pragma unroll
        for (int i = 0; i < 4; ++i) {
            int idx = tid + i * 256;
            int r = idx >> 4, c4 = (idx & 15) * 4;
            size_t row = (size_t)b * S + c * CHUNK + half * 64 + r;
            float4 kv = *(const float4*)&K[row * 1024 + headoff + c4];
            float w = pw[half * 64 + r];
            Ks[r][c4 + 0] = kv.x * w; Ks[r][c4 + 1] = kv.y * w;
            Ks[r][c4 + 2] = kv.z * w; Ks[r][c4 + 3] = kv.w * w;
            *(float4*)&Vs[r][c4] = *(const float4*)&V[row * 1024 + headoff + c4];
        }
        __syncthreads();
        #pragma unroll 8
        for (int lj = 0; lj < 64; ++lj) {
            float a[4], bb[4];
            *(float4*)&a[0]  = *(const float4*)&Ks[lj][ty * 4];
            *(float4*)&bb[0] = *(const float4*)&Vs[lj][tx * 4];
            #pragma unroll
            for (int m = 0; m < 4; ++m)
                #pragma unroll
                for (int n = 0; n < 4; ++n)
                    acc[m][n] = fmaf(a[m], bb[n], acc[m][n]);
        }
    }

    float* out = KV + (((size_t)(b * N_HEADS + h) * NCHUNK + c) << 12);
    #pragma unroll
    for (int m = 0; m < 4; ++m)
        *(float4*)&out[(ty * 4 + m) * 64 + tx * 4] =
            make_float4(acc[m][0], acc[m][1], acc[m][2], acc[m][3]);
}

__global__ __launch_bounds__(256) void scan_kernel(
    const float* __restrict__ KV, float* __restrict__ St)
{
    const int tid = threadIdx.x;
    const size_t base = (size_t)blockIdx.x * NCHUNK * 4096;
    const float dC = powf(DECAY, (float)CHUNK);

    float state[16];
    #pragma unroll
    for (int r = 0; r < 16; ++r) state[r] = 0.f;

    for (int c = 0; c < NCHUNK; ++c) {
        const size_t o = base + (size_t)c * 4096 + tid;
        #pragma unroll
        for (int r = 0; r < 16; ++r) St[o + r * 256] = state[r];
        #pragma unroll
        for (int r = 0; r < 16; ++r) state[r] = dC * (state[r] + KV[o + r * 256]);
    }
}

__global__ __launch_bounds__(256, 1) void attn_chunk_kernel(
    const float* __restrict__ Q, const float* __restrict__ K,
    const float* __restrict__ V, const float* __restrict__ St,
    float* __restrict__ R, int S)
{
    extern __shared__ float sm[];
    float* QsT = sm;                    // [64][132]
    float* KsT = QsT + 64 * 132;        // [64][68]
    float* Vs  = KsT + 64 * 68;         // [64][64]
    float* Ss  = Vs  + 64 * 64;         // [64][132]
    __shared__ float pi[128], pinv[64];

    const int tid = threadIdx.x;
    const int tx = tid & 15;
    const int ty = tid >> 4;
    const int qt = blockIdx.x, h = blockIdx.y, b = blockIdx.z;
    const int i0 = qt * CHUNK;
    const size_t rowbase = (size_t)b * S;
    const int headoff = h * D_HEAD;

    #pragma unroll
    for (int i = 0; i < 8; ++i) {
        int idx = tid + i * 256;
        int q  = idx >> 4;
        int d4 = (idx & 15) * 4;
        float4 v = *(const float4*)&Q[(rowbase + i0 + q) * 1024 + headoff + d4];
        QsT[(d4 + 0) * 132 + q] = v.x; QsT[(d4 + 1) * 132 + q] = v.y;
        QsT[(d4 + 2) * 132 + q] = v.z; QsT[(d4 + 3) * 132 + q] = v.w;
    }
    {
        const float* Sp = St + (((size_t)(b * N_HEADS + h) * NCHUNK + qt) << 12);
        #pragma unroll
        for (int i = 0; i < 4; ++i) {
            int idx = tid + i * 256;
            int d = idx >> 4, e4 = (idx & 15) * 4;
            *(float4*)&KsT[d * 68 + e4] = *(const float4*)&Sp[d * 64 + e4];
        }
    }
    if (tid < 128)      pi[tid]         = powf(DECAY, (float)tid);
    else if (tid < 192) pinv[tid - 128] = powf(DECAY, -(float)(tid - 128));
    __syncthreads();

    float accO[8][4];
    {
        float accSt[8][4] = {};
        #pragma unroll 16
        for (int d = 0; d < 64; ++d) {
            float qv[8], sv[4];
            *(float4*)&qv[0] = *(const float4*)&QsT[d * 132 + ty * 8];
            *(float4*)&qv[4] = *(const float4*)&QsT[d * 132 + ty * 8 + 4];
            *(float4*)&sv[0] = *(const float4*)&KsT[d * 68 + tx * 4];
            #pragma unroll
            for (int m = 0; m < 8; ++m)
                #pragma unroll
                for (int n = 0; n < 4; ++n)
                    accSt[m][n] = fmaf(qv[m], sv[n], accSt[m][n]);
        }
        #pragma unroll
        for (int m = 0; m < 8; ++m) {
            float w = 0.125f * pi[ty * 8 + m];
            #pragma unroll
            for (int n = 0; n < 4; ++n) accO[m][n] = w * accSt[m][n];
        }
    }

    #pragma unroll 1
    for (int jt2 = 0; jt2 < 2; ++jt2) {
        const int j0 = i0 + jt2 * 64;
        __syncthreads();

        #pragma unroll
        for (int i = 0; i < 4; ++i) {
            int idx = tid + i * 256;
            int k  = idx >> 4;
            int d4 = (idx & 15) * 4;
            size_t g = (rowbase + j0 + k) * 1024 + headoff + d4;
            float4 kv = *(const float4*)&K[g];
            KsT[(d4 + 0) * 68 + k] = kv.x; KsT[(d4 + 1) * 68 + k] = kv.y;
            KsT[(d4 + 2) * 68 + k] = kv.z; KsT[(d4 + 3) * 68 + k] = kv.w;
            *(float4*)&Vs[k * 64 + d4] = *(const float4*)&V[g];
        }
        __syncthreads();

        float accS[8][4] = {};
        #pragma unroll 16
        for (int d = 0; d < 64; ++d) {
            float qv[8], kv[4];
            *(float4*)&qv[0] = *(const float4*)&QsT[d * 132 + ty * 8];
            *(float4*)&qv[4] = *(const float4*)&QsT[d * 132 + ty * 8 + 4];
            *(float4*)&kv[0] = *(const float4*)&KsT[d * 68 + tx * 4];
            #pragma unroll
            for (int m = 0; m < 8; ++m)
                #pragma unroll
                for (int n = 0; n < 4; ++n)
                    accS[m][n] = fmaf(qv[m], kv[n], accS[m][n]);
        }

        const float base = powf(DECAY, (float)(i0 - j0)) * 0.125f;
        const int joff = j0 - i0;
        #pragma unroll
        for (int n = 0; n < 4; ++n) {
            int dj = tx * 4 + n;
            float wj = base * pinv[dj];
            float t[8];
            #pragma unroll
            for (int m = 0; m < 8; ++m) {
                int di = ty * 8 + m;
                float w = wj * pi[di];
                if (joff + dj > di) w = 0.f;
                t[m] = accS[m][n] * w;
            }
            *(float4*)&Ss[dj * 132 + ty * 8]     = make_float4(t[0], t[1], t[2], t[3]);
            *(float4*)&Ss[dj * 132 + ty * 8 + 4] = make_float4(t[4], t[5], t[6], t[7]);
        }
        __syncthreads();

        #pragma unroll 16
        for (int k = 0; k < 64; ++k) {
            float sv[8], vv[4];
            *(float4*)&sv[0] = *(const float4*)&Ss[k * 132 + ty * 8];
            *(float4*)&sv[4] = *(const float4*)&Ss[k * 132 + ty * 8 + 4];
            *(float4*)&vv[0] = *(const float4*)&Vs[k * 64 + tx * 4];
            #pragma unroll
            for (int m = 0; m < 8; ++m)
                #pragma unroll
                for (int n = 0; n < 4; ++n)
                    accO[m][n] = fmaf(sv[m], vv[n], accO[m][n]);
        }
    }

    #pragma unroll
    for (int m = 0; m < 8; ++m) {
        *(float4*)&R[(rowbase + i0 + ty * 8 + m) * 1024 + headoff + tx * 4] =
            make_float4(accO[m][0], accO[m][1], accO[m][2], accO[m][3]);
    }
}

// ---------------- LayerNorm + sigmoid gate ----------------
__global__ __launch_bounds__(256) void ln_gate_kernel(
    const float* __restrict__ Rt, const float* __restrict__ Gp,
    const float* __restrict__ gamma, const float* __restrict__ beta,
    float* __restrict__ out)
{
    const int row = blockIdx.x;
    const int tid = threadIdx.x;
    const float* r = Rt + (size_t)row * D_MODEL;

    float s = 0.f, s2 = 0.f;
    #pragma unroll
    for (int c = tid; c < D_MODEL; c += 256) { float v = r[c]; s += v; s2 = fmaf(v, v, s2); }

    __shared__ float red[64];
    #pragma unroll
    for (int off = 16; off; off >>= 1) {
        s  += __shfl_down_sync(0xffffffffu, s,  off);
        s2 += __shfl_down_sync(0xffffffffu, s2, off);
    }
    const int lane = tid & 31, w = tid >> 5;
    if (lane == 0) { red[w] = s; red[32 + w] = s2; }
    __syncthreads();
    if (tid == 0) {
        float S = 0.f, S2 = 0.f;
        #pragma unroll
        for (int i = 0; i < 8; ++i) { S += red[i]; S2 += red[32 + i]; }
        float mu  = S  * (1.f / D_MODEL);
        float var = S2 * (1.f / D_MODEL) - mu * mu;
        red[0] = mu;
        red[1] = rsqrtf(var + 1e-5f);
    }
    __syncthreads();
    const float mu = red[0], inv = red[1];

    const float* gp = Gp + (size_t)row * D_MODEL;
    float* o = out + (size_t)row * D_MODEL;
    #pragma unroll
    for (int c = tid; c < D_MODEL; c += 256) {
        float v = (r[c] - mu) * inv * gamma[c] + beta[c];
        float g = 1.f / (1.f + expf(-gp[c]));
        o[c] = v * g;
    }
}

// ---------------- launch ----------------
extern "C" void kernel_launch(void* const* d_in, const int* in_sizes, int n_in,
                              void* d_out, int out_size)
{
    const float* x     = (const float*)d_in[0];
    const float* Wq    = (const float*)d_in[1];
    const float* bq    = (const float*)d_in[2];
    const float* Wk    = (const float*)d_in[3];
    const float* bk    = (const float*)d_in[4];
    const float* Wv    = (const float*)d_in[5];
    const float* bv    = (const float*)d_in[6];
    const float* Wg    = (const float*)d_in[7];
    const float* bg    = (const float*)d_in[8];
    const float* Wo    = (const float*)d_in[9];
    const float* bo    = (const float*)d_in[10];
    const float* gamma = (const float*)d_in[11];
    const float* beta  = (const float*)d_in[12];
    float* out = (float*)d_out;

    const int M = in_sizes[0] / D_MODEL;   // 4096
    const int B = 2;
    const int S = M / B;                   // 2048

    float *Qd, *Kd, *Vd, *Gpd, *Rd, *NGd, *KVd, *Std, *Xcd, *Wtd;
    cudaGetSymbolAddress((void**)&Qd,  g_Q);
    cudaGetSymbolAddress((void**)&Kd,  g_K);
    cudaGetSymbolAddress((void**)&Vd,  g_V);
    cudaGetSymbolAddress((void**)&Gpd, g_Gp);
    cudaGetSymbolAddress((void**)&Rd,  g_R);
    cudaGetSymbolAddress((void**)&NGd, g_NG);
    cudaGetSymbolAddress((void**)&KVd, g_KV);
    cudaGetSymbolAddress((void**)&Std, g_St);
    cudaGetSymbolAddress((void**)&Xcd, g_Xc);
    cudaGetSymbolAddress((void**)&Wtd, g_Wt);

    // 1) pre-convert (tf32 round; weights transposed)
    cvt_tf32_vec<<<(M * D_MODEL) / 1024, 256>>>(x, Xcd);
    wtrans5_kernel<<<dim3(32, 32, 5), 256>>>(Wq, Wk, Wv, Wg, Wo, Wtd);

    // 2) fused 4-way projection (TF32 tensor cores)
    dim3 pg(D_MODEL / 128, M / 128, 4);
    proj4_kernel<<<pg, 256>>>(Xcd, Wtd, bq, bk, bv, bg, Qd, Kd, Vd, Gpd);

    // 3) chunkwise retention
    kv_kernel<<<dim3(NCHUNK, N_HEADS, B), 256>>>(Kd, Vd, KVd, S);
    scan_kernel<<<B * N_HEADS, 256>>>(KVd, Std);

    const int ATT_SMEM = (64 * 132 + 64 * 68 + 64 * 64 + 64 * 132) * (int)sizeof(float);
    cudaFuncSetAttribute(attn_chunk_kernel, cudaFuncAttributeMaxDynamicSharedMemorySize, ATT_SMEM);
    attn_chunk_kernel<<<dim3(S / CHUNK, N_HEADS, B), 256, ATT_SMEM>>>(Qd, Kd, Vd, Std, Rd, S);

    // 4) LN + gate
    ln_gate_kernel<<<M, 256>>>(Rd, Gpd, gamma, beta, NGd);

    // 5) output projection (convert NG, then TF32 GEMM)
    cvt_tf32_vec<<<(M * D_MODEL) / 1024, 256>>>(NGd, Xcd);
    sgemm_out<<<dim3(D_MODEL / 128, M / 128), 256>>>(
        Xcd, Wtd + (size_t)4 * D_MODEL * D_MODEL, bo, out);
}

// round 13
// speedup vs baseline: 3.4141x; 1.0461x over previous
#include <cuda_runtime.h>
#include <math.h>
#include <stdint.h>

#define D_MODEL 1024
#define N_HEADS 16
#define D_HEAD  64
#define DECAY   0.99f
#define MAXROWS 4096
#define NCHUNK  32
#define CHUNK   64

// ---------------- scratch ----------------
__device__ float g_Q [MAXROWS * D_MODEL];
__device__ float g_K [MAXROWS * D_MODEL];
__device__ float g_V [MAXROWS * D_MODEL];
__device__ float g_Gp[MAXROWS * D_MODEL];
__device__ float g_R [MAXROWS * D_MODEL];
__device__ float g_KV[2 * N_HEADS * NCHUNK * 64 * 64];
__device__ float g_St[2 * N_HEADS * NCHUNK * 64 * 64];
__device__ float g_Xc[MAXROWS * D_MODEL];          // tf32-rounded activations
__device__ float g_Wt[5 * D_MODEL * D_MODEL];      // tf32-rounded transposed weights

__device__ __forceinline__ float tf32r(float x) {
    uint32_t u;
    asm("cvt.rna.tf32.f32 %0, %1;" : "=r"(u) : "f"(x));
    return __uint_as_float(u);
}
__device__ __forceinline__ void mma_tf32(float* d, const uint32_t* a, const uint32_t* b) {
    asm volatile(
        "mma.sync.aligned.m16n8k8.row.col.f32.tf32.tf32.f32 "
        "{%0,%1,%2,%3}, {%4,%5,%6,%7}, {%8,%9}, {%0,%1,%2,%3};\n"
        : "+f"(d[0]), "+f"(d[1]), "+f"(d[2]), "+f"(d[3])
        : "r"(a[0]), "r"(a[1]), "r"(a[2]), "r"(a[3]), "r"(b[0]), "r"(b[1]));
}

// ---------------- pre-conversion ----------------
__global__ __launch_bounds__(256) void cvt_tf32_vec(
    const float* __restrict__ in, float* __restrict__ out)
{
    int i = blockIdx.x * 256 + threadIdx.x;
    float4 v = ((const float4*)in)[i];
    v.x = tf32r(v.x); v.y = tf32r(v.y); v.z = tf32r(v.z); v.w = tf32r(v.w);
    ((float4*)out)[i] = v;
}

// Wt[z][n][k] = tf32(W_z[k][n])
__global__ __launch_bounds__(256) void wtrans5_kernel(
    const float* __restrict__ W0, const float* __restrict__ W1,
    const float* __restrict__ W2, const float* __restrict__ W3,
    const float* __restrict__ W4, float* __restrict__ Wt)
{
    __shared__ float t[32][33];
    const float* W;
    switch (blockIdx.z) {
        case 0: W = W0; break; case 1: W = W1; break;
        case 2: W = W2; break; case 3: W = W3; break;
        default: W = W4; break;
    }
    float* out = Wt + (size_t)blockIdx.z * D_MODEL * D_MODEL;
    const int bx = blockIdx.x * 32, by = blockIdx.y * 32;
    const int tx = threadIdx.x & 31, ty = threadIdx.x >> 5;

    #pragma unroll
    for (int i = 0; i < 4; ++i)
        t[ty * 4 + i][tx] = W[(size_t)(by + ty * 4 + i) * 1024 + bx + tx];
    __syncthreads();
    #pragma unroll
    for (int i = 0; i < 4; ++i)
        out[(size_t)(bx + ty * 4 + i) * 1024 + by + tx] = tf32r(t[tx][ty * 4 + i]);
}

// =======================================================================
// TF32 mma.sync GEMM v3 (proven R8): C = A*W + bias.
// =======================================================================
#define ASTR 20
#define TILEF (128 * ASTR)

__device__ __forceinline__ void gemm_tf32_v3(
    const float* __restrict__ A, const float* __restrict__ Wt,
    const float* __restrict__ bias, float* __restrict__ C,
    int row0, int col0)
{
    __shared__ float As[2][TILEF];
    __shared__ float Bs[2][TILEF];

    const int tid = threadIdx.x;
    const int lane = tid & 31, wid = tid >> 5;
    const int wm = wid >> 2, wn = wid & 3;
    const int lr = lane >> 2, lk = lane & 3;
    const int sr = tid >> 2, sc4 = (tid & 3) << 2;

    float acc[4][4][4] = {};
    float4 ra[2], rb[2];

    #pragma unroll
    for (int i = 0; i < 2; ++i) {
        ra[i] = *(const float4*)&A [(size_t)(row0 + sr + i * 64) * 1024 + sc4];
        rb[i] = *(const float4*)&Wt[(size_t)(col0 + sr + i * 64) * 1024 + sc4];
    }
    #pragma unroll
    for (int i = 0; i < 2; ++i) {
        *(float4*)&As[0][(sr + i * 64) * ASTR + sc4] = ra[i];
        *(float4*)&Bs[0][(sr + i * 64) * ASTR + sc4] = rb[i];
    }
    __syncthreads();

    #pragma unroll 1
    for (int it = 0; it < 64; ++it) {
        const int buf = it & 1;
        if (it < 63) {
            const int k0 = (it + 1) * 16;
            #pragma unroll
            for (int i = 0; i < 2; ++i) {
                ra[i] = *(const float4*)&A [(size_t)(row0 + sr + i * 64) * 1024 + k0 + sc4];
                rb[i] = *(const float4*)&Wt[(size_t)(col0 + sr + i * 64) * 1024 + k0 + sc4];
            }
        }
        const float* Ab = As[buf];
        const float* Bb = Bs[buf];
        #pragma unroll
        for (int ks = 0; ks < 2; ++ks) {
            const int kb = ks * 8 + lk;
            uint32_t af[4][4], bf[4][2];
            #pragma unroll
            for (int mt = 0; mt < 4; ++mt) {
                const float* ap = Ab + (wm * 64 + mt * 16 + lr) * ASTR + kb;
                af[mt][0] = __float_as_uint(ap[0]);
                af[mt][1] = __float_as_uint(ap[8 * ASTR]);
                af[mt][2] = __float_as_uint(ap[4]);
                af[mt][3] = __float_as_uint(ap[8 * ASTR + 4]);
            }
            #pragma unroll
            for (int nt = 0; nt < 4; ++nt) {
                const float* bp = Bb + (wn * 32 + nt * 8 + lr) * ASTR + kb;
                bf[nt][0] = __float_as_uint(bp[0]);
                bf[nt][1] = __float_as_uint(bp[4]);
            }
            #pragma unroll
            for (int mt = 0; mt < 4; ++mt)
                #pragma unroll
                for (int nt = 0; nt < 4; ++nt)
                    mma_tf32(acc[mt][nt], af[mt], bf[nt]);
        }
        if (it < 63) {
            const int nb = buf ^ 1;
            #pragma unroll
            for (int i = 0; i < 2; ++i) {
                *(float4*)&As[nb][(sr + i * 64) * ASTR + sc4] = ra[i];
                *(float4*)&Bs[nb][(sr + i * 64) * ASTR + sc4] = rb[i];
            }
        }
        __syncthreads();
    }

    #pragma unroll
    for (int mt = 0; mt < 4; ++mt) {
        #pragma unroll
        for (int nt = 0; nt < 4; ++nt) {
            int r = row0 + wm * 64 + mt * 16 + lr;
            int c = col0 + wn * 32 + nt * 8 + lk * 2;
            float b0 = bias[c], b1 = bias[c + 1];
            *(float2*)&C[(size_t)r * 1024 + c] =
                make_float2(acc[mt][nt][0] + b0, acc[mt][nt][1] + b1);
            *(float2*)&C[(size_t)(r + 8) * 1024 + c] =
                make_float2(acc[mt][nt][2] + b0, acc[mt][nt][3] + b1);
        }
    }
}

__global__ __launch_bounds__(256, 2) void proj4_kernel(
    const float* __restrict__ xc, const float* __restrict__ Wt,
    const float* __restrict__ bq, const float* __restrict__ bk,
    const float* __restrict__ bv, const float* __restrict__ bg,
    float* __restrict__ Qo, float* __restrict__ Ko,
    float* __restrict__ Vo, float* __restrict__ Go)
{
    const float* bias; float* C;
    switch (blockIdx.z) {
        case 0:  bias = bq; C = Qo; break;
        case 1:  bias = bk; C = Ko; break;
        case 2:  bias = bv; C = Vo; break;
        default: bias = bg; C = Go; break;
    }
    gemm_tf32_v3(xc, Wt + (size_t)blockIdx.z * D_MODEL * D_MODEL, bias, C,
                 blockIdx.y * 128, blockIdx.x * 128);
}

__global__ __launch_bounds__(256, 2) void sgemm_out(
    const float* __restrict__ A, const float* __restrict__ Wt,
    const float* __restrict__ bias, float* __restrict__ C)
{
    gemm_tf32_v3(A, Wt, bias, C, blockIdx.y * 128, blockIdx.x * 128);
}

// =======================================================================
// Chunkwise retention, CHUNK=64.
// stage A: KV_c[d][e] = sum_{lj<64} decay^(-lj) k[lj][d] v[lj][e]
// =======================================================================
__global__ __launch_bounds__(256) void kv_kernel(
    const float* __restrict__ K, const float* __restrict__ V,
    float* __restrict__ KV, int S)
{
    __shared__ float Ks[64][68];
    __shared__ float Vs[64][68];
    __shared__ float pw[64];

    const int tid = threadIdx.x;
    const int tx = tid & 15, ty = tid >> 4;
    const int c = blockIdx.x, h = blockIdx.y, b = blockIdx.z;
    const int headoff = h * D_HEAD;

    if (tid < 64) pw[tid] = powf(DECAY, -(float)tid);
    __syncthreads();

    #pragma unroll
    for (int i = 0; i < 4; ++i) {
        int idx = tid + i * 256;
        int r = idx >> 4, c4 = (idx & 15) * 4;
        size_t row = (size_t)b * S + c * CHUNK + r;
        float4 kv = *(const float4*)&K[row * 1024 + headoff + c4];
        float w = pw[r];
        Ks[r][c4 + 0] = kv.x * w; Ks[r][c4 + 1] = kv.y * w;
        Ks[r][c4 + 2] = kv.z * w; Ks[r][c4 + 3] = kv.w * w;
        *(float4*)&Vs[r][c4] = *(const float4*)&V[row * 1024 + headoff + c4];
    }
    __syncthreads();

    float acc[4][4] = {};
    #pragma unroll 8
    for (int lj = 0; lj < 64; ++lj) {
        float a[4], bb[4];
        *(float4*)&a[0]  = *(const float4*)&Ks[lj][ty * 4];
        *(float4*)&bb[0] = *(const float4*)&Vs[lj][tx * 4];
        #pragma unroll
        for (int m = 0; m < 4; ++m)
            #pragma unroll
            for (int n = 0; n < 4; ++n)
                acc[m][n] = fmaf(a[m], bb[n], acc[m][n]);
    }

    float* out = KV + (((size_t)(b * N_HEADS + h) * NCHUNK + c) << 12);
    #pragma unroll
    for (int m = 0; m < 4; ++m)
        *(float4*)&out[(ty * 4 + m) * 64 + tx * 4] =
            make_float4(acc[m][0], acc[m][1], acc[m][2], acc[m][3]);
}

// stage B: State_c = decay^64 * (State_{c-1} + KV_{c-1})
__global__ __launch_bounds__(256) void scan_kernel(
    const float* __restrict__ KV, float* __restrict__ St)
{
    const int tid = threadIdx.x;
    const size_t base = (size_t)blockIdx.x * NCHUNK * 4096;
    const float dC = powf(DECAY, (float)CHUNK);

    float state[16];
    #pragma unroll
    for (int r = 0; r < 16; ++r) state[r] = 0.f;

    for (int c = 0; c < NCHUNK; ++c) {
        const size_t o = base + (size_t)c * 4096 + tid;
        #pragma unroll
        for (int r = 0; r < 16; ++r) St[o + r * 256] = state[r];
        #pragma unroll
        for (int r = 0; r < 16; ++r) state[r] = dC * (state[r] + KV[o + r * 256]);
    }
}

// =======================================================================
// stage C, CHUNK=64: one block per (chunk, h, b); 64 queries;
// retained = masked-intra(64x64) + 0.125 * decay^li * (q . State_c)
// smem: 4 x [64][68] = 69632 B -> 3 CTAs/SM
// =======================================================================
__global__ __launch_bounds__(256) void attn_chunk_kernel(
    const float* __restrict__ Q, const float* __restrict__ K,
    const float* __restrict__ V, const float* __restrict__ St,
    float* __restrict__ R, int S)
{
    extern __shared__ float sm[];
    float* QsT  = sm;                  // [64][68]  (d, q)
    float* StKs = QsT + 64 * 68;       // [64][68]  State[d][e], then K^T (d, k)
    float* Vs   = StKs + 64 * 68;      // [64][68]  (k, e)
    float* Ss   = Vs + 64 * 68;        // [64][68]  scores^T (k, q)
    __shared__ float pi[64], pinv[64];

    const int tid = threadIdx.x;
    const int tx = tid & 15;           // 4 cols (e or k)
    const int ty = tid >> 4;           // 4 rows (q)
    const int qt = blockIdx.x, h = blockIdx.y, b = blockIdx.z;
    const int i0 = qt * CHUNK;
    const size_t rowbase = (size_t)b * S;
    const int headoff = h * D_HEAD;

    // Q tile 64x64 transposed
    #pragma unroll
    for (int i = 0; i < 4; ++i) {
        int idx = tid + i * 256;
        int q = idx >> 4, d4 = (idx & 15) * 4;
        float4 v = *(const float4*)&Q[(rowbase + i0 + q) * 1024 + headoff + d4];
        QsT[(d4 + 0) * 68 + q] = v.x; QsT[(d4 + 1) * 68 + q] = v.y;
        QsT[(d4 + 2) * 68 + q] = v.z; QsT[(d4 + 3) * 68 + q] = v.w;
    }
    // State_c[d][e]
    {
        const float* Sp = St + (((size_t)(b * N_HEADS + h) * NCHUNK + qt) << 12);
        #pragma unroll
        for (int i = 0; i < 4; ++i) {
            int idx = tid + i * 256;
            int d = idx >> 4, e4 = (idx & 15) * 4;
            *(float4*)&StKs[d * 68 + e4] = *(const float4*)&Sp[d * 64 + e4];
        }
    }
    if (tid < 64)       pi[tid]        = powf(DECAY, (float)tid);
    else if (tid < 128) pinv[tid - 64] = powf(DECAY, -(float)(tid - 64));
    __syncthreads();

    // state GEMM
    float accO[4][4];
    {
        float accSt[4][4] = {};
        #pragma unroll 16
        for (int d = 0; d < 64; ++d) {
            float qv[4], sv[4];
            *(float4*)&qv[0] = *(const float4*)&QsT[d * 68 + ty * 4];
            *(float4*)&sv[0] = *(const float4*)&StKs[d * 68 + tx * 4];
            #pragma unroll
            for (int m = 0; m < 4; ++m)
                #pragma unroll
                for (int n = 0; n < 4; ++n)
                    accSt[m][n] = fmaf(qv[m], sv[n], accSt[m][n]);
        }
        #pragma unroll
        for (int m = 0; m < 4; ++m) {
            float w = 0.125f * pi[ty * 4 + m];
            #pragma unroll
            for (int n = 0; n < 4; ++n) accO[m][n] = w * accSt[m][n];
        }
    }
    __syncthreads();   // done reading StKs as State

    // load K (transposed) + V diagonal tile
    #pragma unroll
    for (int i = 0; i < 4; ++i) {
        int idx = tid + i * 256;
        int k = idx >> 4, d4 = (idx & 15) * 4;
        size_t g = (rowbase + i0 + k) * 1024 + headoff + d4;
        float4 kv = *(const float4*)&K[g];
        StKs[(d4 + 0) * 68 + k] = kv.x; StKs[(d4 + 1) * 68 + k] = kv.y;
        StKs[(d4 + 2) * 68 + k] = kv.z; StKs[(d4 + 3) * 68 + k] = kv.w;
        *(float4*)&Vs[k * 68 + d4] = *(const float4*)&V[g];
    }
    __syncthreads();

    // scores = Q.K^T
    float accS[4][4] = {};
    #pragma unroll 16
    for (int d = 0; d < 64; ++d) {
        float qv[4], kv[4];
        *(float4*)&qv[0] = *(const float4*)&QsT[d * 68 + ty * 4];
        *(float4*)&kv[0] = *(const float4*)&StKs[d * 68 + tx * 4];
        #pragma unroll
        for (int m = 0; m < 4; ++m)
            #pragma unroll
            for (int n = 0; n < 4; ++n)
                accS[m][n] = fmaf(qv[m], kv[n], accS[m][n]);
    }

    // mask + decay, store transposed Ss[k][q]
    #pragma unroll
    for (int n = 0; n < 4; ++n) {
        int dj = tx * 4 + n;
        float wj = 0.125f * pinv[dj];
        float t[4];
        #pragma unroll
        for (int m = 0; m < 4; ++m) {
            int di = ty * 4 + m;
            float w = wj * pi[di];
            if (dj > di) w = 0.f;
            t[m] = accS[m][n] * w;
        }
        *(float4*)&Ss[dj * 68 + ty * 4] = make_float4(t[0], t[1], t[2], t[3]);
    }
    __syncthreads();

    // O += S.V
    #pragma unroll 16
    for (int k = 0; k < 64; ++k) {
        float sv[4], vv[4];
        *(float4*)&sv[0] = *(const float4*)&Ss[k * 68 + ty * 4];
        *(float4*)&vv[0] = *(const float4*)&Vs[k * 68 + tx * 4];
        #pragma unroll
        for (int m = 0; m < 4; ++m)
            #pragma unroll
            for (int n = 0; n < 4; ++n)
                accO[m][n] = fmaf(sv[m], vv[n], accO[m][n]);
    }

    #pragma unroll
    for (int m = 0; m < 4; ++m) {
        *(float4*)&R[(rowbase + i0 + ty * 4 + m) * 1024 + headoff + tx * 4] =
            make_float4(accO[m][0], accO[m][1], accO[m][2], accO[m][3]);
    }
}

// ---------------- LayerNorm + sigmoid gate, fused tf32 round ----------------
__global__ __launch_bounds__(256) void ln_gate_kernel(
    const float* __restrict__ Rt, const float* __restrict__ Gp,
    const float* __restrict__ gamma, const float* __restrict__ beta,
    float* __restrict__ out)
{
    const int row = blockIdx.x;
    const int tid = threadIdx.x;
    const float* r = Rt + (size_t)row * D_MODEL;

    float s = 0.f, s2 = 0.f;
    #pragma unroll
    for (int c = tid; c < D_MODEL; c += 256) { float v = r[c]; s += v; s2 = fmaf(v, v, s2); }

    __shared__ float red[64];
    #pragma unroll
    for (int off = 16; off; off >>= 1) {
        s  += __shfl_down_sync(0xffffffffu, s,  off);
        s2 += __shfl_down_sync(0xffffffffu, s2, off);
    }
    const int lane = tid & 31, w = tid >> 5;
    if (lane == 0) { red[w] = s; red[32 + w] = s2; }
    __syncthreads();
    if (tid == 0) {
        float S = 0.f, S2 = 0.f;
        #pragma unroll
        for (int i = 0; i < 8; ++i) { S += red[i]; S2 += red[32 + i]; }
        float mu  = S  * (1.f / D_MODEL);
        float var = S2 * (1.f / D_MODEL) - mu * mu;
        red[0] = mu;
        red[1] = rsqrtf(var + 1e-5f);
    }
    __syncthreads();
    const float mu = red[0], inv = red[1];

    const float* gp = Gp + (size_t)row * D_MODEL;
    float* o = out + (size_t)row * D_MODEL;
    #pragma unroll
    for (int c = tid; c < D_MODEL; c += 256) {
        float v = (r[c] - mu) * inv * gamma[c] + beta[c];
        float g = 1.f / (1.f + expf(-gp[c]));
        o[c] = tf32r(v * g);
    }
}

// ---------------- launch ----------------
extern "C" void kernel_launch(void* const* d_in, const int* in_sizes, int n_in,
                              void* d_out, int out_size)
{
    const float* x     = (const float*)d_in[0];
    const float* Wq    = (const float*)d_in[1];
    const float* bq    = (const float*)d_in[2];
    const float* Wk    = (const float*)d_in[3];
    const float* bk    = (const float*)d_in[4];
    const float* Wv    = (const float*)d_in[5];
    const float* bv    = (const float*)d_in[6];
    const float* Wg    = (const float*)d_in[7];
    const float* bg    = (const float*)d_in[8];
    const float* Wo    = (const float*)d_in[9];
    const float* bo    = (const float*)d_in[10];
    const float* gamma = (const float*)d_in[11];
    const float* beta  = (const float*)d_in[12];
    float* out = (float*)d_out;

    const int M = in_sizes[0] / D_MODEL;   // 4096
    const int B = 2;
    const int S = M / B;                   // 2048

    float *Qd, *Kd, *Vd, *Gpd, *Rd, *KVd, *Std, *Xcd, *Wtd;
    cudaGetSymbolAddress((void**)&Qd,  g_Q);
    cudaGetSymbolAddress((void**)&Kd,  g_K);
    cudaGetSymbolAddress((void**)&Vd,  g_V);
    cudaGetSymbolAddress((void**)&Gpd, g_Gp);
    cudaGetSymbolAddress((void**)&Rd,  g_R);
    cudaGetSymbolAddress((void**)&KVd, g_KV);
    cudaGetSymbolAddress((void**)&Std, g_St);
    cudaGetSymbolAddress((void**)&Xcd, g_Xc);
    cudaGetSymbolAddress((void**)&Wtd, g_Wt);

    // 1) pre-convert (tf32 round; weights transposed)
    cvt_tf32_vec<<<(M * D_MODEL) / 1024, 256>>>(x, Xcd);
    wtrans5_kernel<<<dim3(32, 32, 5), 256>>>(Wq, Wk, Wv, Wg, Wo, Wtd);

    // 2) fused 4-way projection (TF32 tensor cores)
    dim3 pg(D_MODEL / 128, M / 128, 4);
    proj4_kernel<<<pg, 256>>>(Xcd, Wtd, bq, bk, bv, bg, Qd, Kd, Vd, Gpd);

    // 3) chunkwise retention (CHUNK=64)
    kv_kernel<<<dim3(NCHUNK, N_HEADS, B), 256>>>(Kd, Vd, KVd, S);
    scan_kernel<<<B * N_HEADS, 256>>>(KVd, Std);

    const int ATT_SMEM = 4 * 64 * 68 * (int)sizeof(float);   // 69632
    cudaFuncSetAttribute(attn_chunk_kernel, cudaFuncAttributeMaxDynamicSharedMemorySize, ATT_SMEM);
    attn_chunk_kernel<<<dim3(S / CHUNK, N_HEADS, B), 256, ATT_SMEM>>>(Qd, Kd, Vd, Std, Rd, S);

    // 4) LN + gate (writes tf32-rounded activations directly)
    ln_gate_kernel<<<M, 256>>>(Rd, Gpd, gamma, beta, Xcd);

    // 5) output projection
    sgemm_out<<<dim3(D_MODEL / 128, M / 128), 256>>>(
        Xcd, Wtd + (size_t)4 * D_MODEL * D_MODEL, bo, out);
}

// round 15
// speedup vs baseline: 3.8211x; 1.1192x over previous
#include <cuda_runtime.h>
#include <math.h>
#include <stdint.h>

#define D_MODEL 1024
#define N_HEADS 16
#define D_HEAD  64
#define DECAY   0.99f
#define MAXROWS 4096
#define NCHUNK  32
#define CHUNK   64

// ---------------- scratch ----------------
__device__ float g_Q [MAXROWS * D_MODEL];
__device__ float g_K [MAXROWS * D_MODEL];
__device__ float g_V [MAXROWS * D_MODEL];
__device__ float g_Gp[MAXROWS * D_MODEL];
__device__ float g_R [MAXROWS * D_MODEL];
__device__ float g_NG[MAXROWS * D_MODEL];
__device__ float g_KV[2 * N_HEADS * NCHUNK * 64 * 64];
__device__ float g_St[2 * N_HEADS * NCHUNK * 64 * 64];

__device__ __forceinline__ float tf32r(float x) {
    uint32_t u;
    asm("cvt.rna.tf32.f32 %0, %1;" : "=r"(u) : "f"(x));
    return __uint_as_float(u);
}
__device__ __forceinline__ void mma_tf32(float* d, const uint32_t* a, const uint32_t* b) {
    asm volatile(
        "mma.sync.aligned.m16n8k8.row.col.f32.tf32.tf32.f32 "
        "{%0,%1,%2,%3}, {%4,%5,%6,%7}, {%8,%9}, {%0,%1,%2,%3};\n"
        : "+f"(d[0]), "+f"(d[1]), "+f"(d[2]), "+f"(d[3])
        : "r"(a[0]), "r"(a[1]), "r"(a[2]), "r"(a[3]), "r"(b[0]), "r"(b[1]));
}

// =======================================================================
// TF32 mma.sync GEMM v4: C = A*W + bias, raw fp32 inputs (tf32 round at
// staging). A row-major [M][K]; W row-major [K][N] read directly.
// A smem: [128][20] row-major (proven). B smem: [16][136] k-major —
// fragment addr = 136*kb + n == 8*lk + lr (mod 32): conflict-free.
// 128x128 tile, BK=16, register-staged double buffer, 8 warps of 64x32.
// =======================================================================
#define ASTR  20
#define ATILE (128 * ASTR)     // 2560 floats
#define BSTR  136
#define BTILE (16 * BSTR)      // 2176 floats

__device__ __forceinline__ void gemm_tf32_v4(
    const float* __restrict__ A, const float* __restrict__ W,
    const float* __restrict__ bias, float* __restrict__ C,
    int row0, int col0)
{
    __shared__ float As[2][ATILE];
    __shared__ float Bs[2][BTILE];

    const int tid = threadIdx.x;
    const int lane = tid & 31, wid = tid >> 5;
    const int wm = wid >> 2, wn = wid & 3;
    const int lr = lane >> 2, lk = lane & 3;
    const int sr = tid >> 2, sc4 = (tid & 3) << 2;     // A staging: 64(+64) rows x 16k
    const int bkr = tid >> 5, bc4 = (tid & 31) << 2;   // B staging: 8(+8) k-rows x 128n

    float acc[4][4][4] = {};
    float4 ra[2], rb[2];

    // prologue: LDG k0=0
    #pragma unroll
    for (int i = 0; i < 2; ++i) {
        ra[i] = *(const float4*)&A[(size_t)(row0 + sr + i * 64) * 1024 + sc4];
        rb[i] = *(const float4*)&W[(size_t)(bkr + i * 8) * 1024 + col0 + bc4];
    }
    #pragma unroll
    for (int i = 0; i < 2; ++i) {
        *(float4*)&As[0][(sr + i * 64) * ASTR + sc4] = make_float4(
            tf32r(ra[i].x), tf32r(ra[i].y), tf32r(ra[i].z), tf32r(ra[i].w));
        *(float4*)&Bs[0][(bkr + i * 8) * BSTR + bc4] = make_float4(
            tf32r(rb[i].x), tf32r(rb[i].y), tf32r(rb[i].z), tf32r(rb[i].w));
    }
    __syncthreads();

    #pragma unroll 1
    for (int it = 0; it < 64; ++it) {
        const int buf = it & 1;
        if (it < 63) {
            const int k0 = (it + 1) * 16;
            #pragma unroll
            for (int i = 0; i < 2; ++i) {
                ra[i] = *(const float4*)&A[(size_t)(row0 + sr + i * 64) * 1024 + k0 + sc4];
                rb[i] = *(const float4*)&W[(size_t)(k0 + bkr + i * 8) * 1024 + col0 + bc4];
            }
        }
        const float* Ab = As[buf];
        const float* Bb = Bs[buf];
        #pragma unroll
        for (int ks = 0; ks < 2; ++ks) {
            const int kb = ks * 8 + lk;
            uint32_t af[4][4], bf[4][2];
            #pragma unroll
            for (int mt = 0; mt < 4; ++mt) {
                const float* ap = Ab + (wm * 64 + mt * 16 + lr) * ASTR + kb;
                af[mt][0] = __float_as_uint(ap[0]);
                af[mt][1] = __float_as_uint(ap[8 * ASTR]);
                af[mt][2] = __float_as_uint(ap[4]);
                af[mt][3] = __float_as_uint(ap[8 * ASTR + 4]);
            }
            #pragma unroll
            for (int nt = 0; nt < 4; ++nt) {
                const float* bp = Bb + kb * BSTR + wn * 32 + nt * 8 + lr;
                bf[nt][0] = __float_as_uint(bp[0]);
                bf[nt][1] = __float_as_uint(bp[4 * BSTR]);
            }
            #pragma unroll
            for (int mt = 0; mt < 4; ++mt)
                #pragma unroll
                for (int nt = 0; nt < 4; ++nt)
                    mma_tf32(acc[mt][nt], af[mt], bf[nt]);
        }
        if (it < 63) {
            const int nb = buf ^ 1;
            #pragma unroll
            for (int i = 0; i < 2; ++i) {
                *(float4*)&As[nb][(sr + i * 64) * ASTR + sc4] = make_float4(
                    tf32r(ra[i].x), tf32r(ra[i].y), tf32r(ra[i].z), tf32r(ra[i].w));
                *(float4*)&Bs[nb][(bkr + i * 8) * BSTR + bc4] = make_float4(
                    tf32r(rb[i].x), tf32r(rb[i].y), tf32r(rb[i].z), tf32r(rb[i].w));
            }
        }
        __syncthreads();
    }

    // epilogue (proven mapping)
    #pragma unroll
    for (int mt = 0; mt < 4; ++mt) {
        #pragma unroll
        for (int nt = 0; nt < 4; ++nt) {
            int r = row0 + wm * 64 + mt * 16 + lr;
            int c = col0 + wn * 32 + nt * 8 + lk * 2;
            float b0 = bias[c], b1 = bias[c + 1];
            *(float2*)&C[(size_t)r * 1024 + c] =
                make_float2(acc[mt][nt][0] + b0, acc[mt][nt][1] + b1);
            *(float2*)&C[(size_t)(r + 8) * 1024 + c] =
                make_float2(acc[mt][nt][2] + b0, acc[mt][nt][3] + b1);
        }
    }
}

__global__ __launch_bounds__(256, 2) void proj4_kernel(
    const float* __restrict__ x,
    const float* __restrict__ Wq, const float* __restrict__ bq, float* __restrict__ Qo,
    const float* __restrict__ Wk, const float* __restrict__ bk, float* __restrict__ Ko,
    const float* __restrict__ Wv, const float* __restrict__ bv, float* __restrict__ Vo,
    const float* __restrict__ Wg, const float* __restrict__ bg, float* __restrict__ Go)
{
    const float* W; const float* bias; float* C;
    switch (blockIdx.z) {
        case 0:  W = Wq; bias = bq; C = Qo; break;
        case 1:  W = Wk; bias = bk; C = Ko; break;
        case 2:  W = Wv; bias = bv; C = Vo; break;
        default: W = Wg; bias = bg; C = Go; break;
    }
    gemm_tf32_v4(x, W, bias, C, blockIdx.y * 128, blockIdx.x * 128);
}

__global__ __launch_bounds__(256, 2) void sgemm_out(
    const float* __restrict__ A, const float* __restrict__ W,
    const float* __restrict__ bias, float* __restrict__ C)
{
    gemm_tf32_v4(A, W, bias, C, blockIdx.y * 128, blockIdx.x * 128);
}

// =======================================================================
// Chunkwise retention, CHUNK=64 (proven R13).
// =======================================================================
__global__ __launch_bounds__(256) void kv_kernel(
    const float* __restrict__ K, const float* __restrict__ V,
    float* __restrict__ KV, int S)
{
    __shared__ float Ks[64][68];
    __shared__ float Vs[64][68];
    __shared__ float pw[64];

    const int tid = threadIdx.x;
    const int tx = tid & 15, ty = tid >> 4;
    const int c = blockIdx.x, h = blockIdx.y, b = blockIdx.z;
    const int headoff = h * D_HEAD;

    if (tid < 64) pw[tid] = powf(DECAY, -(float)tid);
    __syncthreads();

    #pragma unroll
    for (int i = 0; i < 4; ++i) {
        int idx = tid + i * 256;
        int r = idx >> 4, c4 = (idx & 15) * 4;
        size_t row = (size_t)b * S + c * CHUNK + r;
        float4 kv = *(const float4*)&K[row * 1024 + headoff + c4];
        float w = pw[r];
        Ks[r][c4 + 0] = kv.x * w; Ks[r][c4 + 1] = kv.y * w;
        Ks[r][c4 + 2] = kv.z * w; Ks[r][c4 + 3] = kv.w * w;
        *(float4*)&Vs[r][c4] = *(const float4*)&V[row * 1024 + headoff + c4];
    }
    __syncthreads();

    float acc[4][4] = {};
    #pragma unroll 8
    for (int lj = 0; lj < 64; ++lj) {
        float a[4], bb[4];
        *(float4*)&a[0]  = *(const float4*)&Ks[lj][ty * 4];
        *(float4*)&bb[0] = *(const float4*)&Vs[lj][tx * 4];
        #pragma unroll
        for (int m = 0; m < 4; ++m)
            #pragma unroll
            for (int n = 0; n < 4; ++n)
                acc[m][n] = fmaf(a[m], bb[n], acc[m][n]);
    }

    float* out = KV + (((size_t)(b * N_HEADS + h) * NCHUNK + c) << 12);
    #pragma unroll
    for (int m = 0; m < 4; ++m)
        *(float4*)&out[(ty * 4 + m) * 64 + tx * 4] =
            make_float4(acc[m][0], acc[m][1], acc[m][2], acc[m][3]);
}

__global__ __launch_bounds__(256) void scan_kernel(
    const float* __restrict__ KV, float* __restrict__ St)
{
    const int tid = threadIdx.x;
    const size_t base = (size_t)blockIdx.x * NCHUNK * 4096;
    const float dC = powf(DECAY, (float)CHUNK);

    float state[16];
    #pragma unroll
    for (int r = 0; r < 16; ++r) state[r] = 0.f;

    for (int c = 0; c < NCHUNK; ++c) {
        const size_t o = base + (size_t)c * 4096 + tid;
        #pragma unroll
        for (int r = 0; r < 16; ++r) St[o + r * 256] = state[r];
        #pragma unroll
        for (int r = 0; r < 16; ++r) state[r] = dC * (state[r] + KV[o + r * 256]);
    }
}

__global__ __launch_bounds__(256) void attn_chunk_kernel(
    const float* __restrict__ Q, const float* __restrict__ K,
    const float* __restrict__ V, const float* __restrict__ St,
    float* __restrict__ R, int S)
{
    extern __shared__ float sm[];
    float* QsT  = sm;                  // [64][68]
    float* StKs = QsT + 64 * 68;       // [64][68]
    float* Vs   = StKs + 64 * 68;      // [64][68]
    float* Ss   = Vs + 64 * 68;        // [64][68]
    __shared__ float pi[64], pinv[64];

    const int tid = threadIdx.x;
    const int tx = tid & 15;
    const int ty = tid >> 4;
    const int qt = blockIdx.x, h = blockIdx.y, b = blockIdx.z;
    const int i0 = qt * CHUNK;
    const size_t rowbase = (size_t)b * S;
    const int headoff = h * D_HEAD;

    #pragma unroll
    for (int i = 0; i < 4; ++i) {
        int idx = tid + i * 256;
        int q = idx >> 4, d4 = (idx & 15) * 4;
        float4 v = *(const float4*)&Q[(rowbase + i0 + q) * 1024 + headoff + d4];
        QsT[(d4 + 0) * 68 + q] = v.x; QsT[(d4 + 1) * 68 + q] = v.y;
        QsT[(d4 + 2) * 68 + q] = v.z; QsT[(d4 + 3) * 68 + q] = v.w;
    }
    {
        const float* Sp = St + (((size_t)(b * N_HEADS + h) * NCHUNK + qt) << 12);
        #pragma unroll
        for (int i = 0; i < 4; ++i) {
            int idx = tid + i * 256;
            int d = idx >> 4, e4 = (idx & 15) * 4;
            *(float4*)&StKs[d * 68 + e4] = *(const float4*)&Sp[d * 64 + e4];
        }
    }
    if (tid < 64)       pi[tid]        = powf(DECAY, (float)tid);
    else if (tid < 128) pinv[tid - 64] = powf(DECAY, -(float)(tid - 64));
    __syncthreads();

    float accO[4][4];
    {
        float accSt[4][4] = {};
        #pragma unroll 16
        for (int d = 0; d < 64; ++d) {
            float qv[4], sv[4];
            *(float4*)&qv[0] = *(const float4*)&QsT[d * 68 + ty * 4];
            *(float4*)&sv[0] = *(const float4*)&StKs[d * 68 + tx * 4];
            #pragma unroll
            for (int m = 0; m < 4; ++m)
                #pragma unroll
                for (int n = 0; n < 4; ++n)
                    accSt[m][n] = fmaf(qv[m], sv[n], accSt[m][n]);
        }
        #pragma unroll
        for (int m = 0; m < 4; ++m) {
            float w = 0.125f * pi[ty * 4 + m];
            #pragma unroll
            for (int n = 0; n < 4; ++n) accO[m][n] = w * accSt[m][n];
        }
    }
    __syncthreads();

    #pragma unroll
    for (int i = 0; i < 4; ++i) {
        int idx = tid + i * 256;
        int k = idx >> 4, d4 = (idx & 15) * 4;
        size_t g = (rowbase + i0 + k) * 1024 + headoff + d4;
        float4 kv = *(const float4*)&K[g];
        StKs[(d4 + 0) * 68 + k] = kv.x; StKs[(d4 + 1) * 68 + k] = kv.y;
        StKs[(d4 + 2) * 68 + k] = kv.z; StKs[(d4 + 3) * 68 + k] = kv.w;
        *(float4*)&Vs[k * 68 + d4] = *(const float4*)&V[g];
    }
    __syncthreads();

    float accS[4][4] = {};
    #pragma unroll 16
    for (int d = 0; d < 64; ++d) {
        float qv[4], kv[4];
        *(float4*)&qv[0] = *(const float4*)&QsT[d * 68 + ty * 4];
        *(float4*)&kv[0] = *(const float4*)&StKs[d * 68 + tx * 4];
        #pragma unroll
        for (int m = 0; m < 4; ++m)
            #pragma unroll
            for (int n = 0; n < 4; ++n)
                accS[m][n] = fmaf(qv[m], kv[n], accS[m][n]);
    }

    #pragma unroll
    for (int n = 0; n < 4; ++n) {
        int dj = tx * 4 + n;
        float wj = 0.125f * pinv[dj];
        float t[4];
        #pragma unroll
        for (int m = 0; m < 4; ++m) {
            int di = ty * 4 + m;
            float w = wj * pi[di];
            if (dj > di) w = 0.f;
            t[m] = accS[m][n] * w;
        }
        *(float4*)&Ss[dj * 68 + ty * 4] = make_float4(t[0], t[1], t[2], t[3]);
    }
    __syncthreads();

    #pragma unroll 16
    for (int k = 0; k < 64; ++k) {
        float sv[4], vv[4];
        *(float4*)&sv[0] = *(const float4*)&Ss[k * 68 + ty * 4];
        *(float4*)&vv[0] = *(const float4*)&Vs[k * 68 + tx * 4];
        #pragma unroll
        for (int m = 0; m < 4; ++m)
            #pragma unroll
            for (int n = 0; n < 4; ++n)
                accO[m][n] = fmaf(sv[m], vv[n], accO[m][n]);
    }

    #pragma unroll
    for (int m = 0; m < 4; ++m) {
        *(float4*)&R[(rowbase + i0 + ty * 4 + m) * 1024 + headoff + tx * 4] =
            make_float4(accO[m][0], accO[m][1], accO[m][2], accO[m][3]);
    }
}

// ---------------- LayerNorm + sigmoid gate ----------------
__global__ __launch_bounds__(256) void ln_gate_kernel(
    const float* __restrict__ Rt, const float* __restrict__ Gp,
    const float* __restrict__ gamma, const float* __restrict__ beta,
    float* __restrict__ out)
{
    const int row = blockIdx.x;
    const int tid = threadIdx.x;
    const float* r = Rt + (size_t)row * D_MODEL;

    float s = 0.f, s2 = 0.f;
    #pragma unroll
    for (int c = tid; c < D_MODEL; c += 256) { float v = r[c]; s += v; s2 = fmaf(v, v, s2); }

    __shared__ float red[64];
    #pragma unroll
    for (int off = 16; off; off >>= 1) {
        s  += __shfl_down_sync(0xffffffffu, s,  off);
        s2 += __shfl_down_sync(0xffffffffu, s2, off);
    }
    const int lane = tid & 31, w = tid >> 5;
    if (lane == 0) { red[w] = s; red[32 + w] = s2; }
    __syncthreads();
    if (tid == 0) {
        float S = 0.f, S2 = 0.f;
        #pragma unroll
        for (int i = 0; i < 8; ++i) { S += red[i]; S2 += red[32 + i]; }
        float mu  = S  * (1.f / D_MODEL);
        float var = S2 * (1.f / D_MODEL) - mu * mu;
        red[0] = mu;
        red[1] = rsqrtf(var + 1e-5f);
    }
    __syncthreads();
    const float mu = red[0], inv = red[1];

    const float* gp = Gp + (size_t)row * D_MODEL;
    float* o = out + (size_t)row * D_MODEL;
    #pragma unroll
    for (int c = tid; c < D_MODEL; c += 256) {
        float v = (r[c] - mu) * inv * gamma[c] + beta[c];
        float g = 1.f / (1.f + expf(-gp[c]));
        o[c] = v * g;
    }
}

// ---------------- launch ----------------
extern "C" void kernel_launch(void* const* d_in, const int* in_sizes, int n_in,
                              void* d_out, int out_size)
{
    const float* x     = (const float*)d_in[0];
    const float* Wq    = (const float*)d_in[1];
    const float* bq    = (const float*)d_in[2];
    const float* Wk    = (const float*)d_in[3];
    const float* bk    = (const float*)d_in[4];
    const float* Wv    = (const float*)d_in[5];
    const float* bv    = (const float*)d_in[6];
    const float* Wg    = (const float*)d_in[7];
    const float* bg    = (const float*)d_in[8];
    const float* Wo    = (const float*)d_in[9];
    const float* bo    = (const float*)d_in[10];
    const float* gamma = (const float*)d_in[11];
    const float* beta  = (const float*)d_in[12];
    float* out = (float*)d_out;

    const int M = in_sizes[0] / D_MODEL;   // 4096
    const int B = 2;
    const int S = M / B;                   // 2048

    float *Qd, *Kd, *Vd, *Gpd, *Rd, *NGd, *KVd, *Std;
    cudaGetSymbolAddress((void**)&Qd,  g_Q);
    cudaGetSymbolAddress((void**)&Kd,  g_K);
    cudaGetSymbolAddress((void**)&Vd,  g_V);
    cudaGetSymbolAddress((void**)&Gpd, g_Gp);
    cudaGetSymbolAddress((void**)&Rd,  g_R);
    cudaGetSymbolAddress((void**)&NGd, g_NG);
    cudaGetSymbolAddress((void**)&KVd, g_KV);
    cudaGetSymbolAddress((void**)&Std, g_St);

    // 1) fused 4-way projection (TF32 tensor cores, cvt fused in staging)
    dim3 pg(D_MODEL / 128, M / 128, 4);
    proj4_kernel<<<pg, 256>>>(x, Wq, bq, Qd, Wk, bk, Kd, Wv, bv, Vd, Wg, bg, Gpd);

    // 2) chunkwise retention (CHUNK=64)
    kv_kernel<<<dim3(NCHUNK, N_HEADS, B), 256>>>(Kd, Vd, KVd, S);
    scan_kernel<<<B * N_HEADS, 256>>>(KVd, Std);

    const int ATT_SMEM = 4 * 64 * 68 * (int)sizeof(float);   // 69632
    cudaFuncSetAttribute(attn_chunk_kernel, cudaFuncAttributeMaxDynamicSharedMemorySize, ATT_SMEM);
    attn_chunk_kernel<<<dim3(S / CHUNK, N_HEADS, B), 256, ATT_SMEM>>>(Qd, Kd, Vd, Std, Rd, S);

    // 3) LN + gate
    ln_gate_kernel<<<M, 256>>>(Rd, Gpd, gamma, beta, NGd);

    // 4) output projection
    sgemm_out<<<dim3(D_MODEL / 128, M / 128), 256>>>(NGd, Wo, bo, out);
}